// round 5
// baseline (speedup 1.0000x reference)
#include <cuda_runtime.h>
#include <cuda_bf16.h>
#include <cstdint>

#define NB 16
#define CD 256
#define HW 4096
#define KA 512
#define ROWS (NB*HW)   // 65536

// ---------------- scratch (__device__ globals; no allocations) ----------------
__device__ __align__(16) float g_A0[(size_t)ROWS * KA];              // 128 MB
__device__ __align__(16) __nv_bfloat16 g_Xh[(size_t)ROWS * CD];      // X^T hi [n][hw][c]
__device__ __align__(16) __nv_bfloat16 g_Xl[(size_t)ROWS * CD];      // X^T lo
__device__ __align__(16) __nv_bfloat16 g_Shj[(size_t)NB*KA*CD];      // S hi [n][j][c]
__device__ __align__(16) __nv_bfloat16 g_Slj[(size_t)NB*KA*CD];      // S lo [n][j][c]
__device__ __align__(16) __nv_bfloat16 g_Shc[(size_t)NB*CD*KA];      // S hi [n][c][j]
__device__ __align__(16) __nv_bfloat16 g_Slc[(size_t)NB*CD*KA];      // S lo [n][c][j]
__device__ float g_invnorm[ROWS];
__device__ float g_colsum[KA];
__device__ float g_cvec[KA];

// ---------------- helpers ----------------
__device__ __forceinline__ uint32_t smem_u32(const void* p) {
    uint32_t a;
    asm("{ .reg .u64 t; cvta.to.shared.u64 t, %1; cvt.u32.u64 %0, t; }" : "=r"(a) : "l"(p));
    return a;
}
__device__ __forceinline__ uint32_t swz(uint32_t o) { return o ^ ((o >> 3) & 0x70); }
__device__ __forceinline__ uint32_t pack_bf2(__nv_bfloat16 a, __nv_bfloat16 b) {
    return (uint32_t)__bfloat16_as_ushort(a) | ((uint32_t)__bfloat16_as_ushort(b) << 16);
}
__device__ __forceinline__ void split_bf(float f, __nv_bfloat16& h, __nv_bfloat16& l) {
    h = __float2bfloat16(f);
    l = __float2bfloat16(f - __bfloat162float(h));
}
__device__ __forceinline__ void ldm4(uint32_t addr, uint32_t r[4]) {
    asm volatile("ldmatrix.sync.aligned.m8n8.x4.shared.b16 {%0,%1,%2,%3}, [%4];"
        : "=r"(r[0]), "=r"(r[1]), "=r"(r[2]), "=r"(r[3]) : "r"(addr));
}
__device__ __forceinline__ void mma16816(float c[4], const uint32_t a[4],
                                         uint32_t b0, uint32_t b1) {
    asm volatile("mma.sync.aligned.m16n8k16.row.col.f32.bf16.bf16.f32 "
        "{%0,%1,%2,%3}, {%4,%5,%6,%7}, {%8,%9}, {%0,%1,%2,%3};"
        : "+f"(c[0]), "+f"(c[1]), "+f"(c[2]), "+f"(c[3])
        : "r"(a[0]), "r"(a[1]), "r"(a[2]), "r"(a[3]), "r"(b0), "r"(b1));
}
__device__ __forceinline__ uint32_t afrag_addr(uint32_t base, int mbase, int s, int lane) {
    int row = mbase + (lane & 7) + ((lane >> 3) & 1) * 8;
    int unit = 2 * s + (lane >> 4);
    return base + swz((uint32_t)(row * 128 + unit * 16));
}
__device__ __forceinline__ uint32_t bfrag_addr(uint32_t base, int nbase, int s, int lane) {
    int row = nbase + (lane & 7) + ((lane >> 4) & 1) * 8;
    int unit = 2 * s + ((lane >> 3) & 1);
    return base + swz((uint32_t)(row * 128 + unit * 16));
}
#define CPA16(s, g) asm volatile("cp.async.cg.shared.global [%0], [%1], 16;" :: "r"(s), "l"(g))
#define CP_COMMIT() asm volatile("cp.async.commit_group;" ::: "memory")
#define CP_WAIT1()  asm volatile("cp.async.wait_group 1;" ::: "memory")
#define CP_WAIT0()  asm volatile("cp.async.wait_group 0;" ::: "memory")

// ---------------- small kernels (unchanged from round 4) ----------------
__global__ void zero_colsum_kernel() { g_colsum[threadIdx.x] = 0.0f; }

__global__ void norm_kernel(const float* __restrict__ x) {
    int i = blockIdx.x * blockDim.x + threadIdx.x;
    int n = i >> 12, hw = i & 4095;
    const float* p = x + (size_t)n * CD * HW + hw;
    float acc = 0.0f;
#pragma unroll 16
    for (int c = 0; c < CD; ++c) { float v = p[(size_t)c * HW]; acc = fmaf(v, v, acc); }
    g_invnorm[i] = 1.0f / fmaxf(sqrtf(acc), 1e-12f);
}

__global__ void xt_kernel(const float* __restrict__ x) {
    __shared__ float t[32][33];
    int n = blockIdx.z, hw0 = blockIdx.x * 32, c0 = blockIdx.y * 32;
    int tx = threadIdx.x, ty = threadIdx.y;
#pragma unroll
    for (int r = 0; r < 32; r += 8)
        t[ty + r][tx] = x[((size_t)n * CD + c0 + ty + r) * HW + hw0 + tx];
    __syncthreads();
#pragma unroll
    for (int r = 0; r < 32; r += 8) {
        float v = t[tx][ty + r];
        size_t o = ((size_t)n * HW + hw0 + ty + r) * CD + c0 + tx;
        __nv_bfloat16 h, l; split_bf(v, h, l);
        g_Xh[o] = h; g_Xl[o] = l;
    }
}

__global__ void gather_cj(const float* __restrict__ x, const int* __restrict__ idx) {
    int t = blockIdx.x * blockDim.x + threadIdx.x;
    int j = t & (KA - 1);
    int nc = t >> 9;
    int n = nc >> 8;
    int pos = idx[j];
    float v = x[(size_t)nc * HW + pos] * g_invnorm[n * HW + pos];
    __nv_bfloat16 h, l; split_bf(v, h, l);
    g_Shc[t] = h; g_Slc[t] = l;
}
__global__ void gather_jc(const float* __restrict__ x, const int* __restrict__ idx) {
    int t = blockIdx.x * blockDim.x + threadIdx.x;
    int c = t & (CD - 1);
    int nj = t >> 8;
    int j = nj & (KA - 1);
    int n = nj >> 9;
    int pos = idx[j];
    float v = x[((size_t)n * CD + c) * HW + pos] * g_invnorm[n * HW + pos];
    __nv_bfloat16 h, l; split_bf(v, h, l);
    g_Shj[t] = h; g_Slj[t] = l;
}

__global__ void recip_kernel() {
    int j = threadIdx.x;
    g_cvec[j] = 1.0f / fmaxf(g_colsum[j], 1e-30f);
    g_colsum[j] = 0.0f;
}

__global__ __launch_bounds__(256) void sk_pass() {
    __shared__ float cred[KA];
    int tid = threadIdx.x;
    cred[tid] = 0.0f; cred[tid + 256] = 0.0f;
    __syncthreads();
    int warp = tid >> 5, lane = tid & 31;
    float4 c4[4];
#pragma unroll
    for (int m = 0; m < 4; ++m) c4[m] = ((const float4*)g_cvec)[m * 32 + lane];
    float4 ca[4];
#pragma unroll
    for (int m = 0; m < 4; ++m) ca[m] = make_float4(0.f, 0.f, 0.f, 0.f);
    size_t rbase = (size_t)blockIdx.x * 128 + warp * 16;
    for (int t = 0; t < 16; ++t) {
        const float4* row = (const float4*)(g_A0 + (rbase + t) * KA);
        float4 a[4]; float d = 0.0f;
#pragma unroll
        for (int m = 0; m < 4; ++m) {
            a[m] = row[m * 32 + lane];
            d += a[m].x * c4[m].x + a[m].y * c4[m].y + a[m].z * c4[m].z + a[m].w * c4[m].w;
        }
#pragma unroll
        for (int s = 16; s > 0; s >>= 1) d += __shfl_xor_sync(0xffffffffu, d, s);
        float r = 1.0f / fmaxf(d, 1e-30f);
#pragma unroll
        for (int m = 0; m < 4; ++m) {
            ca[m].x = fmaf(r, a[m].x, ca[m].x); ca[m].y = fmaf(r, a[m].y, ca[m].y);
            ca[m].z = fmaf(r, a[m].z, ca[m].z); ca[m].w = fmaf(r, a[m].w, ca[m].w);
        }
    }
#pragma unroll
    for (int m = 0; m < 4; ++m) {
        int base = (m * 32 + lane) * 4;
        atomicAdd(&cred[base + 0], ca[m].x); atomicAdd(&cred[base + 1], ca[m].y);
        atomicAdd(&cred[base + 2], ca[m].z); atomicAdd(&cred[base + 3], ca[m].w);
    }
    __syncthreads();
    atomicAdd(&g_colsum[tid], cred[tid]);
    atomicAdd(&g_colsum[tid + 256], cred[tid + 256]);
}

// ================= score GEMM: 2-stage cp.async pipeline + fused colsum =================
// SMEM: [0..512) colred(128 floats); stage s at 4096+s*65536: AH 0, AL 16K, BH 32K, BL 48K
#define S_ST(s) (4096 + (s)*65536)
#define S_AH 0
#define S_AL 16384
#define S_BH 32768
#define S_BL 49152
#define SCORE_SMEM (4096 + 131072)

__global__ __launch_bounds__(256, 1) void score_mma() {
    extern __shared__ char smem[];
    uint32_t sb = smem_u32(smem);
    float* colred = (float*)smem;
    int tid = threadIdx.x, lane = tid & 31, w = tid >> 5;
    int n = blockIdx.z, hw0 = blockIdx.x * 128, j0 = blockIdx.y * 128;
    int wm = (w & 3) * 32, wn = (w >> 2) * 64;

    float acc[2][8][4];
#pragma unroll
    for (int a = 0; a < 2; ++a)
#pragma unroll
        for (int b = 0; b < 8; ++b)
#pragma unroll
            for (int c = 0; c < 4; ++c) acc[a][b][c] = 0.0f;

    int crow = tid >> 1, chalf = tid & 1;
    const uint4* aH = (const uint4*)(g_Xh + ((size_t)n * HW + hw0 + crow) * CD);
    const uint4* aL = (const uint4*)(g_Xl + ((size_t)n * HW + hw0 + crow) * CD);
    const uint4* bH = (const uint4*)(g_Shj + ((size_t)n * KA + j0 + crow) * CD);
    const uint4* bL = (const uint4*)(g_Slj + ((size_t)n * KA + j0 + crow) * CD);

    auto issue = [&](int ch, int st) {
        uint32_t base = sb + S_ST(st);
#pragma unroll
        for (int q = 0; q < 4; ++q) {
            int unit = chalf * 4 + q;
            uint32_t off = swz((uint32_t)(crow * 128 + unit * 16));
            int gi = ch * 8 + unit;
            CPA16(base + S_AH + off, aH + gi);
            CPA16(base + S_AL + off, aL + gi);
            CPA16(base + S_BH + off, bH + gi);
            CPA16(base + S_BL + off, bL + gi);
        }
    };

    issue(0, 0); CP_COMMIT();
#pragma unroll 1
    for (int ch = 0; ch < 4; ++ch) {
        if (ch < 3) { issue(ch + 1, (ch + 1) & 1); CP_COMMIT(); CP_WAIT1(); }
        else CP_WAIT0();
        __syncthreads();
        uint32_t tb = sb + S_ST(ch & 1);
#pragma unroll
        for (int s = 0; s < 4; ++s) {
            uint32_t ah[2][4], al[2][4];
#pragma unroll
            for (int mt = 0; mt < 2; ++mt) {
                ldm4(afrag_addr(tb + S_AH, wm + mt * 16, s, lane), ah[mt]);
                ldm4(afrag_addr(tb + S_AL, wm + mt * 16, s, lane), al[mt]);
            }
#pragma unroll
            for (int ng = 0; ng < 4; ++ng) {
                uint32_t bh[4], bl[4];
                ldm4(bfrag_addr(tb + S_BH, wn + ng * 16, s, lane), bh);
                ldm4(bfrag_addr(tb + S_BL, wn + ng * 16, s, lane), bl);
                // term-major ordering: dependent MMAs on same acc spaced by 4
                mma16816(acc[0][2*ng],   ah[0], bh[0], bh[1]);
                mma16816(acc[1][2*ng],   ah[1], bh[0], bh[1]);
                mma16816(acc[0][2*ng+1], ah[0], bh[2], bh[3]);
                mma16816(acc[1][2*ng+1], ah[1], bh[2], bh[3]);
                mma16816(acc[0][2*ng],   ah[0], bl[0], bl[1]);
                mma16816(acc[1][2*ng],   ah[1], bl[0], bl[1]);
                mma16816(acc[0][2*ng+1], ah[0], bl[2], bl[3]);
                mma16816(acc[1][2*ng+1], ah[1], bl[2], bl[3]);
                mma16816(acc[0][2*ng],   al[0], bh[0], bh[1]);
                mma16816(acc[1][2*ng],   al[1], bh[0], bh[1]);
                mma16816(acc[0][2*ng+1], al[0], bh[2], bh[3]);
                mma16816(acc[1][2*ng+1], al[1], bh[2], bh[3]);
            }
        }
        __syncthreads();
    }

    // epilogue: exp + A0 store + fused first column-sum
    if (tid < 128) colred[tid] = 0.0f;
    __syncthreads();
    float colp[16];
#pragma unroll
    for (int e = 0; e < 16; ++e) colp[e] = 0.0f;
#pragma unroll
    for (int mt = 0; mt < 2; ++mt) {
        int i0 = n * HW + hw0 + wm + mt * 16 + (lane >> 2);
        int i1 = i0 + 8;
        float s0 = g_invnorm[i0] * (1.0f / 0.3f);
        float s1 = g_invnorm[i1] * (1.0f / 0.3f);
        float* r0 = g_A0 + (size_t)i0 * KA + j0 + wn + (lane & 3) * 2;
        float* r1 = g_A0 + (size_t)i1 * KA + j0 + wn + (lane & 3) * 2;
#pragma unroll
        for (int nt = 0; nt < 8; ++nt) {
            float e0 = __expf(acc[mt][nt][0] * s0), e1 = __expf(acc[mt][nt][1] * s0);
            float e2 = __expf(acc[mt][nt][2] * s1), e3 = __expf(acc[mt][nt][3] * s1);
            *(float2*)(r0 + nt * 8) = make_float2(e0, e1);
            *(float2*)(r1 + nt * 8) = make_float2(e2, e3);
            colp[nt * 2]     += e0 + e2;
            colp[nt * 2 + 1] += e1 + e3;
        }
    }
#pragma unroll
    for (int nt = 0; nt < 8; ++nt) {
        int cl = wn + (lane & 3) * 2 + nt * 8;
        atomicAdd(&colred[cl], colp[nt * 2]);
        atomicAdd(&colred[cl + 1], colp[nt * 2 + 1]);
    }
    __syncthreads();
    if (tid < 128) atomicAdd(&g_colsum[j0 + tid], colred[tid]);
}

// ================= reconstruct GEMM: pipeline + staged conversion =================
// SMEM: [0..512) dsum(128f); [512..2560) cvec(512f); stage s at 4096+s*65536:
//   AH 0, AL 16K, RAW 32K (128 rows x 256B, unit-xor swizzle); BH/BL single at 135168/151552
#define R_ST(s) (4096 + (s)*65536)
#define R_AH 0
#define R_AL 16384
#define R_RAW 32768
#define R_BH (4096 + 131072)
#define R_BL (4096 + 147456)
#define RECON_SMEM (4096 + 163840)

__global__ __launch_bounds__(256, 1) void recon_mma(float* __restrict__ out) {
    extern __shared__ char smem[];
    uint32_t sb = smem_u32(smem);
    float* red = (float*)smem;
    float* cs = (float*)(smem + 512);
    int tid = threadIdx.x, lane = tid & 31, w = tid >> 5;
    int n = blockIdx.z, hw0 = blockIdx.x * 128, c0 = blockIdx.y * 128;
    int wm = (w & 3) * 32, wn = (w >> 2) * 64;

    if (tid < 128) red[tid] = 0.0f;
    cs[tid] = g_cvec[tid];
    cs[256 + tid] = g_cvec[256 + tid];

    float acc[2][8][4];
#pragma unroll
    for (int a = 0; a < 2; ++a)
#pragma unroll
        for (int b = 0; b < 8; ++b)
#pragma unroll
            for (int c = 0; c < 4; ++c) acc[a][b][c] = 0.0f;

    int crow = tid >> 1, chalf = tid & 1;
    const uint4* aH = (const uint4*)(g_Shc + ((size_t)n * CD + c0 + crow) * KA);
    const uint4* aL = (const uint4*)(g_Slc + ((size_t)n * CD + c0 + crow) * KA);
    const char* arow = (const char*)(g_A0 + ((size_t)(n * HW + hw0 + crow)) * KA);

    auto issue = [&](int ch, int st) {
        uint32_t base = sb + R_ST(st);
#pragma unroll
        for (int q = 0; q < 4; ++q) {
            int unit = chalf * 4 + q;
            uint32_t off = swz((uint32_t)(crow * 128 + unit * 16));
            int gi = ch * 8 + unit;
            CPA16(base + R_AH + off, aH + gi);
            CPA16(base + R_AL + off, aL + gi);
        }
#pragma unroll
        for (int q = 0; q < 8; ++q) {
            int u = chalf * 8 + q;
            uint32_t roff = (uint32_t)(crow * 256 + ((u ^ (crow & 15)) * 16));
            CPA16(base + R_RAW + roff, arow + ch * 256 + u * 16);
        }
    };

    __syncthreads();   // red/cs visible
    issue(0, 0); CP_COMMIT();
#pragma unroll 1
    for (int ch = 0; ch < 8; ++ch) {
        if (ch < 7) { issue(ch + 1, (ch + 1) & 1); CP_COMMIT(); CP_WAIT1(); }
        else CP_WAIT0();
        __syncthreads();   // raw+A ready; prev mma done with BH/BL
        uint32_t tb = sb + R_ST(ch & 1);
        // convert raw fp32 (A0) * c -> BH/BL bf16 hi/lo; accumulate d
        {
            int k0 = ch * 64;
            float dp = 0.0f;
#pragma unroll
            for (int q = 0; q < 4; ++q) {
                int u0 = chalf * 8 + q * 2;
                int u1 = u0 + 1;
                float4 v0 = *(float4*)(smem + tb - sb + R_RAW + crow * 256 + ((u0 ^ (crow & 15)) * 16));
                float4 v1 = *(float4*)(smem + tb - sb + R_RAW + crow * 256 + ((u1 ^ (crow & 15)) * 16));
                int jb = k0 + u0 * 4;
                v0.x *= cs[jb+0]; v0.y *= cs[jb+1]; v0.z *= cs[jb+2]; v0.w *= cs[jb+3];
                v1.x *= cs[jb+4]; v1.y *= cs[jb+5]; v1.z *= cs[jb+6]; v1.w *= cs[jb+7];
                dp += v0.x + v0.y + v0.z + v0.w + v1.x + v1.y + v1.z + v1.w;
                __nv_bfloat16 h[8], l[8];
                split_bf(v0.x, h[0], l[0]); split_bf(v0.y, h[1], l[1]);
                split_bf(v0.z, h[2], l[2]); split_bf(v0.w, h[3], l[3]);
                split_bf(v1.x, h[4], l[4]); split_bf(v1.y, h[5], l[5]);
                split_bf(v1.z, h[6], l[6]); split_bf(v1.w, h[7], l[7]);
                uint32_t off = swz((uint32_t)(crow * 128 + (chalf * 4 + q) * 16));
                *(uint4*)(smem + R_BH + off) =
                    make_uint4(pack_bf2(h[0],h[1]), pack_bf2(h[2],h[3]),
                               pack_bf2(h[4],h[5]), pack_bf2(h[6],h[7]));
                *(uint4*)(smem + R_BL + off) =
                    make_uint4(pack_bf2(l[0],l[1]), pack_bf2(l[2],l[3]),
                               pack_bf2(l[4],l[5]), pack_bf2(l[6],l[7]));
            }
            atomicAdd(&red[crow], dp);
        }
        __syncthreads();   // BH/BL ready
#pragma unroll
        for (int s = 0; s < 4; ++s) {
            uint32_t ah[2][4], al[2][4];
#pragma unroll
            for (int mt = 0; mt < 2; ++mt) {
                ldm4(afrag_addr(tb + R_AH, wm + mt * 16, s, lane), ah[mt]);
                ldm4(afrag_addr(tb + R_AL, wm + mt * 16, s, lane), al[mt]);
            }
#pragma unroll
            for (int ng = 0; ng < 4; ++ng) {
                uint32_t bh[4], bl[4];
                ldm4(bfrag_addr(sb + R_BH, wn + ng * 16, s, lane), bh);
                ldm4(bfrag_addr(sb + R_BL, wn + ng * 16, s, lane), bl);
                mma16816(acc[0][2*ng],   ah[0], bh[0], bh[1]);
                mma16816(acc[1][2*ng],   ah[1], bh[0], bh[1]);
                mma16816(acc[0][2*ng+1], ah[0], bh[2], bh[3]);
                mma16816(acc[1][2*ng+1], ah[1], bh[2], bh[3]);
                mma16816(acc[0][2*ng],   ah[0], bl[0], bl[1]);
                mma16816(acc[1][2*ng],   ah[1], bl[0], bl[1]);
                mma16816(acc[0][2*ng+1], ah[0], bl[2], bl[3]);
                mma16816(acc[1][2*ng+1], ah[1], bl[2], bl[3]);
                mma16816(acc[0][2*ng],   al[0], bh[0], bh[1]);
                mma16816(acc[1][2*ng],   al[1], bh[0], bh[1]);
                mma16816(acc[0][2*ng+1], al[0], bh[2], bh[3]);
                mma16816(acc[1][2*ng+1], al[1], bh[2], bh[3]);
            }
        }
        __syncthreads();   // stage + BH/BL free for reuse
    }

    if (tid < 128) red[tid] = 1.0f / fmaxf(red[tid], 1e-30f);
    __syncthreads();

#pragma unroll
    for (int mt = 0; mt < 2; ++mt) {
        int c = c0 + wm + mt * 16 + (lane >> 2);
        int nl = wn + (lane & 3) * 2;
        float* o0 = out + ((size_t)n * CD + c) * HW + hw0 + nl;
        float* o1 = out + ((size_t)n * CD + c + 8) * HW + hw0 + nl;
#pragma unroll
        for (int nt = 0; nt < 8; ++nt) {
            float rx = red[nl + nt * 8], ry = red[nl + nt * 8 + 1];
            *(float2*)(o0 + nt * 8) = make_float2(acc[mt][nt][0] * rx, acc[mt][nt][1] * ry);
            *(float2*)(o1 + nt * 8) = make_float2(acc[mt][nt][2] * rx, acc[mt][nt][3] * ry);
        }
    }
}

// ----------------------------------------------------------------
extern "C" void kernel_launch(void* const* d_in, const int* in_sizes, int n_in,
                              void* d_out, int out_size) {
    const float* x = (const float*)d_in[0];
    const int* idx = (const int*)d_in[1];
    float* out = (float*)d_out;

    cudaFuncSetAttribute(score_mma, cudaFuncAttributeMaxDynamicSharedMemorySize, SCORE_SMEM);
    cudaFuncSetAttribute(recon_mma, cudaFuncAttributeMaxDynamicSharedMemorySize, RECON_SMEM);

    zero_colsum_kernel<<<1, KA>>>();
    norm_kernel<<<ROWS / 256, 256>>>(x);
    xt_kernel<<<dim3(HW / 32, CD / 32, NB), dim3(32, 8)>>>(x);
    gather_cj<<<(NB * CD * KA) / 256, 256>>>(x, idx);
    gather_jc<<<(NB * KA * CD) / 256, 256>>>(x, idx);

    score_mma<<<dim3(HW / 128, KA / 128, NB), 256, SCORE_SMEM>>>();   // writes A0 + colsum0

    recip_kernel<<<1, KA>>>();                       // c1
    for (int it = 0; it < 3; ++it) {
        sk_pass<<<ROWS / 128, 256>>>();
        recip_kernel<<<1, KA>>>();                   // c2, c3, c4
    }
    recon_mma<<<dim3(HW / 128, CD / 128, NB), 256, RECON_SMEM>>>(out);
}

// round 6
// speedup vs baseline: 1.2795x; 1.2795x over previous
#include <cuda_runtime.h>
#include <cuda_bf16.h>
#include <cuda_fp16.h>
#include <cstdint>

#define NB 16
#define CD 256
#define HW 4096
#define KA 512
#define ROWS (NB*HW)   // 65536

// ---------------- scratch (__device__ globals; no allocations) ----------------
__device__ __align__(16) __half g_A0[(size_t)ROWS * KA];             // 64 MB (fp16)
__device__ __align__(16) __nv_bfloat16 g_Xh[(size_t)ROWS * CD];      // X^T hi [n][hw][c]
__device__ __align__(16) __nv_bfloat16 g_Xl[(size_t)ROWS * CD];      // X^T lo
__device__ __align__(16) __nv_bfloat16 g_Shj[(size_t)NB*KA*CD];      // S hi [n][j][c]
__device__ __align__(16) __nv_bfloat16 g_Slj[(size_t)NB*KA*CD];      // S lo [n][j][c]
__device__ __align__(16) __nv_bfloat16 g_Shc[(size_t)NB*CD*KA];      // S hi [n][c][j]
__device__ __align__(16) __nv_bfloat16 g_Slc[(size_t)NB*CD*KA];      // S lo [n][c][j]
__device__ float g_invnorm[ROWS];
__device__ float g_colsum[KA];
__device__ float g_cvec[KA];

// ---------------- helpers ----------------
__device__ __forceinline__ uint32_t smem_u32(const void* p) {
    uint32_t a;
    asm("{ .reg .u64 t; cvta.to.shared.u64 t, %1; cvt.u32.u64 %0, t; }" : "=r"(a) : "l"(p));
    return a;
}
__device__ __forceinline__ uint32_t swz(uint32_t o) { return o ^ ((o >> 3) & 0x70); }
__device__ __forceinline__ uint32_t pack_bf2(__nv_bfloat16 a, __nv_bfloat16 b) {
    return (uint32_t)__bfloat16_as_ushort(a) | ((uint32_t)__bfloat16_as_ushort(b) << 16);
}
__device__ __forceinline__ void split_bf(float f, __nv_bfloat16& h, __nv_bfloat16& l) {
    h = __float2bfloat16(f);
    l = __float2bfloat16(f - __bfloat162float(h));
}
__device__ __forceinline__ void ldm4(uint32_t addr, uint32_t r[4]) {
    asm volatile("ldmatrix.sync.aligned.m8n8.x4.shared.b16 {%0,%1,%2,%3}, [%4];"
        : "=r"(r[0]), "=r"(r[1]), "=r"(r[2]), "=r"(r[3]) : "r"(addr));
}
__device__ __forceinline__ void mma16816(float c[4], const uint32_t a[4],
                                         uint32_t b0, uint32_t b1) {
    asm volatile("mma.sync.aligned.m16n8k16.row.col.f32.bf16.bf16.f32 "
        "{%0,%1,%2,%3}, {%4,%5,%6,%7}, {%8,%9}, {%0,%1,%2,%3};"
        : "+f"(c[0]), "+f"(c[1]), "+f"(c[2]), "+f"(c[3])
        : "r"(a[0]), "r"(a[1]), "r"(a[2]), "r"(a[3]), "r"(b0), "r"(b1));
}
__device__ __forceinline__ uint32_t afrag_addr(uint32_t base, int mbase, int s, int lane) {
    int row = mbase + (lane & 7) + ((lane >> 3) & 1) * 8;
    int unit = 2 * s + (lane >> 4);
    return base + swz((uint32_t)(row * 128 + unit * 16));
}
__device__ __forceinline__ uint32_t bfrag_addr(uint32_t base, int nbase, int s, int lane) {
    int row = nbase + (lane & 7) + ((lane >> 4) & 1) * 8;
    int unit = 2 * s + ((lane >> 3) & 1);
    return base + swz((uint32_t)(row * 128 + unit * 16));
}

// SMEM layout (dynamic): red/cvec + 4 x 16KB tiles (round-4 structure, 2 CTA/SM)
#define OFF_DS   0          // 128 floats
#define OFF_CV   512        // 512 floats
#define OFF_AH   4096
#define OFF_AL   (4096 + 16384)
#define OFF_BH   (4096 + 32768)
#define OFF_BL   (4096 + 49152)
#define TC_SMEM  (4096 + 65536)   // 69632

// ---------------- small kernels ----------------
__global__ void zero_colsum_kernel() { g_colsum[threadIdx.x] = 0.0f; }

__global__ void norm_kernel(const float* __restrict__ x) {
    int i = blockIdx.x * blockDim.x + threadIdx.x;
    int n = i >> 12, hw = i & 4095;
    const float* p = x + (size_t)n * CD * HW + hw;
    float acc = 0.0f;
#pragma unroll 16
    for (int c = 0; c < CD; ++c) { float v = p[(size_t)c * HW]; acc = fmaf(v, v, acc); }
    g_invnorm[i] = 1.0f / fmaxf(sqrtf(acc), 1e-12f);
}

__global__ void xt_kernel(const float* __restrict__ x) {
    __shared__ float t[32][33];
    int n = blockIdx.z, hw0 = blockIdx.x * 32, c0 = blockIdx.y * 32;
    int tx = threadIdx.x, ty = threadIdx.y;
#pragma unroll
    for (int r = 0; r < 32; r += 8)
        t[ty + r][tx] = x[((size_t)n * CD + c0 + ty + r) * HW + hw0 + tx];
    __syncthreads();
#pragma unroll
    for (int r = 0; r < 32; r += 8) {
        float v = t[tx][ty + r];
        size_t o = ((size_t)n * HW + hw0 + ty + r) * CD + c0 + tx;
        __nv_bfloat16 h, l; split_bf(v, h, l);
        g_Xh[o] = h; g_Xl[o] = l;
    }
}

__global__ void gather_cj(const float* __restrict__ x, const int* __restrict__ idx) {
    int t = blockIdx.x * blockDim.x + threadIdx.x;
    int j = t & (KA - 1);
    int nc = t >> 9;
    int n = nc >> 8;
    int pos = idx[j];
    float v = x[(size_t)nc * HW + pos] * g_invnorm[n * HW + pos];
    __nv_bfloat16 h, l; split_bf(v, h, l);
    g_Shc[t] = h; g_Slc[t] = l;
}
__global__ void gather_jc(const float* __restrict__ x, const int* __restrict__ idx) {
    int t = blockIdx.x * blockDim.x + threadIdx.x;
    int c = t & (CD - 1);
    int nj = t >> 8;
    int j = nj & (KA - 1);
    int n = nj >> 9;
    int pos = idx[j];
    float v = x[((size_t)n * CD + c) * HW + pos] * g_invnorm[n * HW + pos];
    __nv_bfloat16 h, l; split_bf(v, h, l);
    g_Shj[t] = h; g_Slj[t] = l;
}

__global__ void recip_kernel() {
    int j = threadIdx.x;
    g_cvec[j] = 1.0f / fmaxf(g_colsum[j], 1e-30f);
    g_colsum[j] = 0.0f;
}

// fused Sinkhorn pass on fp16 A0: r_i = 1/(A0_i.c); colsum += r_i*A0_i
__global__ __launch_bounds__(256) void sk_pass() {
    __shared__ float cred[KA];
    int tid = threadIdx.x;
    cred[tid] = 0.0f; cred[tid + 256] = 0.0f;
    __syncthreads();
    int warp = tid >> 5, lane = tid & 31;
    float cv[16];
#pragma unroll
    for (int e = 0; e < 8; ++e) { cv[e] = g_cvec[lane * 8 + e]; cv[8 + e] = g_cvec[256 + lane * 8 + e]; }
    float ca[16];
#pragma unroll
    for (int e = 0; e < 16; ++e) ca[e] = 0.0f;
    size_t rbase = (size_t)blockIdx.x * 128 + warp * 16;
    for (int t = 0; t < 16; ++t) {
        const uint4* row = (const uint4*)(g_A0 + (rbase + t) * KA);
        uint4 u0 = row[lane], u1 = row[lane + 32];
        float a[16];
        {
            const __half2* h0 = (const __half2*)&u0;
            const __half2* h1 = (const __half2*)&u1;
#pragma unroll
            for (int k = 0; k < 4; ++k) {
                float2 f0 = __half22float2(h0[k]);
                float2 f1 = __half22float2(h1[k]);
                a[2*k] = f0.x; a[2*k+1] = f0.y;
                a[8 + 2*k] = f1.x; a[8 + 2*k+1] = f1.y;
            }
        }
        float d = 0.0f;
#pragma unroll
        for (int e = 0; e < 16; ++e) d = fmaf(a[e], cv[e], d);
#pragma unroll
        for (int s = 16; s > 0; s >>= 1) d += __shfl_xor_sync(0xffffffffu, d, s);
        float r = 1.0f / fmaxf(d, 1e-30f);
#pragma unroll
        for (int e = 0; e < 16; ++e) ca[e] = fmaf(r, a[e], ca[e]);
    }
#pragma unroll
    for (int e = 0; e < 8; ++e) {
        atomicAdd(&cred[lane * 8 + e], ca[e]);
        atomicAdd(&cred[256 + lane * 8 + e], ca[8 + e]);
    }
    __syncthreads();
    atomicAdd(&g_colsum[tid], cred[tid]);
    atomicAdd(&g_colsum[tid + 256], cred[tid + 256]);
}

// ================= score GEMM (round-4 structure + fused colsum + fp16 store) =================
__global__ __launch_bounds__(256, 2) void score_mma() {
    extern __shared__ char smem[];
    uint32_t sb = smem_u32(smem);
    float* colred = (float*)smem;   // 128 floats at OFF_DS
    int tid = threadIdx.x, lane = tid & 31, w = tid >> 5;
    int n = blockIdx.z, hw0 = blockIdx.x * 128, j0 = blockIdx.y * 128;
    int wm = (w & 3) * 32, wn = (w >> 2) * 64;

    float acc[2][8][4];
#pragma unroll
    for (int a = 0; a < 2; ++a)
#pragma unroll
        for (int b = 0; b < 8; ++b)
#pragma unroll
            for (int c = 0; c < 4; ++c) acc[a][b][c] = 0.0f;

    int crow = tid >> 1, chalf = tid & 1;
    const uint4* aH = (const uint4*)(g_Xh + ((size_t)n * HW + hw0 + crow) * CD);
    const uint4* aL = (const uint4*)(g_Xl + ((size_t)n * HW + hw0 + crow) * CD);
    const uint4* bH = (const uint4*)(g_Shj + ((size_t)n * KA + j0 + crow) * CD);
    const uint4* bL = (const uint4*)(g_Slj + ((size_t)n * KA + j0 + crow) * CD);

    for (int ch = 0; ch < 4; ++ch) {
#pragma unroll
        for (int q = 0; q < 4; ++q) {
            int unit = chalf * 4 + q;
            uint32_t off = swz((uint32_t)(crow * 128 + unit * 16));
            int gi = ch * 8 + unit;
            *(uint4*)(smem + OFF_AH + off) = aH[gi];
            *(uint4*)(smem + OFF_AL + off) = aL[gi];
            *(uint4*)(smem + OFF_BH + off) = bH[gi];
            *(uint4*)(smem + OFF_BL + off) = bL[gi];
        }
        __syncthreads();
#pragma unroll
        for (int s = 0; s < 4; ++s) {
            uint32_t ah[2][4], al[2][4];
#pragma unroll
            for (int mt = 0; mt < 2; ++mt) {
                ldm4(afrag_addr(sb + OFF_AH, wm + mt * 16, s, lane), ah[mt]);
                ldm4(afrag_addr(sb + OFF_AL, wm + mt * 16, s, lane), al[mt]);
            }
#pragma unroll
            for (int ng = 0; ng < 4; ++ng) {
                uint32_t bh[4], bl[4];
                ldm4(bfrag_addr(sb + OFF_BH, wn + ng * 16, s, lane), bh);
                ldm4(bfrag_addr(sb + OFF_BL, wn + ng * 16, s, lane), bl);
                // term-major: same-acc MMAs spaced 4 apart
                mma16816(acc[0][2*ng],   ah[0], bh[0], bh[1]);
                mma16816(acc[1][2*ng],   ah[1], bh[0], bh[1]);
                mma16816(acc[0][2*ng+1], ah[0], bh[2], bh[3]);
                mma16816(acc[1][2*ng+1], ah[1], bh[2], bh[3]);
                mma16816(acc[0][2*ng],   ah[0], bl[0], bl[1]);
                mma16816(acc[1][2*ng],   ah[1], bl[0], bl[1]);
                mma16816(acc[0][2*ng+1], ah[0], bl[2], bl[3]);
                mma16816(acc[1][2*ng+1], ah[1], bl[2], bl[3]);
                mma16816(acc[0][2*ng],   al[0], bh[0], bh[1]);
                mma16816(acc[1][2*ng],   al[1], bh[0], bh[1]);
                mma16816(acc[0][2*ng+1], al[0], bh[2], bh[3]);
                mma16816(acc[1][2*ng+1], al[1], bh[2], bh[3]);
            }
        }
        __syncthreads();
    }

    // epilogue: exp -> fp16 store + fused first column-sum (from rounded values)
    if (tid < 128) colred[tid] = 0.0f;
    __syncthreads();
    float colp[16];
#pragma unroll
    for (int e = 0; e < 16; ++e) colp[e] = 0.0f;
#pragma unroll
    for (int mt = 0; mt < 2; ++mt) {
        int i0 = n * HW + hw0 + wm + mt * 16 + (lane >> 2);
        int i1 = i0 + 8;
        float s0 = g_invnorm[i0] * (1.0f / 0.3f);
        float s1 = g_invnorm[i1] * (1.0f / 0.3f);
        __half* r0 = g_A0 + (size_t)i0 * KA + j0 + wn + (lane & 3) * 2;
        __half* r1 = g_A0 + (size_t)i1 * KA + j0 + wn + (lane & 3) * 2;
#pragma unroll
        for (int nt = 0; nt < 8; ++nt) {
            __half h0 = __float2half(__expf(acc[mt][nt][0] * s0));
            __half h1 = __float2half(__expf(acc[mt][nt][1] * s0));
            __half h2 = __float2half(__expf(acc[mt][nt][2] * s1));
            __half h3 = __float2half(__expf(acc[mt][nt][3] * s1));
            *(__half2*)(r0 + nt * 8) = __halves2half2(h0, h1);
            *(__half2*)(r1 + nt * 8) = __halves2half2(h2, h3);
            colp[nt * 2]     += __half2float(h0) + __half2float(h2);
            colp[nt * 2 + 1] += __half2float(h1) + __half2float(h3);
        }
    }
#pragma unroll
    for (int nt = 0; nt < 8; ++nt) {
        int cl = wn + (lane & 3) * 2 + nt * 8;
        atomicAdd(&colred[cl], colp[nt * 2]);
        atomicAdd(&colred[cl + 1], colp[nt * 2 + 1]);
    }
    __syncthreads();
    if (tid < 128) atomicAdd(&g_colsum[j0 + tid], colred[tid]);
}

// ================= reconstruct GEMM (round-4 structure, fp16 A0 loads) =================
__global__ __launch_bounds__(256, 2) void recon_mma(float* __restrict__ out) {
    extern __shared__ char smem[];
    uint32_t sb = smem_u32(smem);
    float* red = (float*)smem;
    float* cs  = (float*)(smem + OFF_CV);
    int tid = threadIdx.x, lane = tid & 31, w = tid >> 5;
    int n = blockIdx.z, hw0 = blockIdx.x * 128, c0 = blockIdx.y * 128;
    int wm = (w & 3) * 32, wn = (w >> 2) * 64;

    if (tid < 128) red[tid] = 0.0f;
    cs[tid] = g_cvec[tid];
    cs[256 + tid] = g_cvec[256 + tid];

    float acc[2][8][4];
#pragma unroll
    for (int a = 0; a < 2; ++a)
#pragma unroll
        for (int b = 0; b < 8; ++b)
#pragma unroll
            for (int c = 0; c < 4; ++c) acc[a][b][c] = 0.0f;

    int crow = tid >> 1, chalf = tid & 1;
    const uint4* aH = (const uint4*)(g_Shc + ((size_t)n * CD + c0 + crow) * KA);
    const uint4* aL = (const uint4*)(g_Slc + ((size_t)n * CD + c0 + crow) * KA);
    const uint4* arow4 = (const uint4*)(g_A0 + ((size_t)(n * HW + hw0 + crow)) * KA);
    __syncthreads();

    for (int ch = 0; ch < 8; ++ch) {
        int k0 = ch * 64;
        // A tile (S hi/lo straight copy)
#pragma unroll
        for (int q = 0; q < 4; ++q) {
            int unit = chalf * 4 + q;
            uint32_t off = swz((uint32_t)(crow * 128 + unit * 16));
            int gi = ch * 8 + unit;
            *(uint4*)(smem + OFF_AH + off) = aH[gi];
            *(uint4*)(smem + OFF_AL + off) = aL[gi];
        }
        // B tile: fp16 A0 * c -> hi/lo bf16 + row-sum d
        {
            float dp = 0.0f;
#pragma unroll
            for (int q = 0; q < 4; ++q) {
                uint4 u = arow4[ch * 8 + chalf * 4 + q];   // 8 halfs
                const __half2* hp = (const __half2*)&u;
                int jb = k0 + (chalf * 4 + q) * 8;
                float v[8];
#pragma unroll
                for (int k = 0; k < 4; ++k) {
                    float2 f = __half22float2(hp[k]);
                    v[2*k]   = f.x * cs[jb + 2*k];
                    v[2*k+1] = f.y * cs[jb + 2*k+1];
                }
                dp += v[0]+v[1]+v[2]+v[3]+v[4]+v[5]+v[6]+v[7];
                __nv_bfloat16 h[8], l[8];
#pragma unroll
                for (int k = 0; k < 8; ++k) split_bf(v[k], h[k], l[k]);
                uint32_t off = swz((uint32_t)(crow * 128 + (chalf * 4 + q) * 16));
                *(uint4*)(smem + OFF_BH + off) =
                    make_uint4(pack_bf2(h[0],h[1]), pack_bf2(h[2],h[3]),
                               pack_bf2(h[4],h[5]), pack_bf2(h[6],h[7]));
                *(uint4*)(smem + OFF_BL + off) =
                    make_uint4(pack_bf2(l[0],l[1]), pack_bf2(l[2],l[3]),
                               pack_bf2(l[4],l[5]), pack_bf2(l[6],l[7]));
            }
            atomicAdd(&red[crow], dp);
        }
        __syncthreads();
#pragma unroll
        for (int s = 0; s < 4; ++s) {
            uint32_t ah[2][4], al[2][4];
#pragma unroll
            for (int mt = 0; mt < 2; ++mt) {
                ldm4(afrag_addr(sb + OFF_AH, wm + mt * 16, s, lane), ah[mt]);
                ldm4(afrag_addr(sb + OFF_AL, wm + mt * 16, s, lane), al[mt]);
            }
#pragma unroll
            for (int ng = 0; ng < 4; ++ng) {
                uint32_t bh[4], bl[4];
                ldm4(bfrag_addr(sb + OFF_BH, wn + ng * 16, s, lane), bh);
                ldm4(bfrag_addr(sb + OFF_BL, wn + ng * 16, s, lane), bl);
                mma16816(acc[0][2*ng],   ah[0], bh[0], bh[1]);
                mma16816(acc[1][2*ng],   ah[1], bh[0], bh[1]);
                mma16816(acc[0][2*ng+1], ah[0], bh[2], bh[3]);
                mma16816(acc[1][2*ng+1], ah[1], bh[2], bh[3]);
                mma16816(acc[0][2*ng],   ah[0], bl[0], bl[1]);
                mma16816(acc[1][2*ng],   ah[1], bl[0], bl[1]);
                mma16816(acc[0][2*ng+1], ah[0], bl[2], bl[3]);
                mma16816(acc[1][2*ng+1], ah[1], bl[2], bl[3]);
                mma16816(acc[0][2*ng],   al[0], bh[0], bh[1]);
                mma16816(acc[1][2*ng],   al[1], bh[0], bh[1]);
                mma16816(acc[0][2*ng+1], al[0], bh[2], bh[3]);
                mma16816(acc[1][2*ng+1], al[1], bh[2], bh[3]);
            }
        }
        __syncthreads();
    }

    if (tid < 128) red[tid] = 1.0f / fmaxf(red[tid], 1e-30f);
    __syncthreads();

#pragma unroll
    for (int mt = 0; mt < 2; ++mt) {
        int c = c0 + wm + mt * 16 + (lane >> 2);
        int nl = wn + (lane & 3) * 2;
        float* o0 = out + ((size_t)n * CD + c) * HW + hw0 + nl;
        float* o1 = out + ((size_t)n * CD + c + 8) * HW + hw0 + nl;
#pragma unroll
        for (int nt = 0; nt < 8; ++nt) {
            float rx = red[nl + nt * 8], ry = red[nl + nt * 8 + 1];
            *(float2*)(o0 + nt * 8) = make_float2(acc[mt][nt][0] * rx, acc[mt][nt][1] * ry);
            *(float2*)(o1 + nt * 8) = make_float2(acc[mt][nt][2] * rx, acc[mt][nt][3] * ry);
        }
    }
}

// ----------------------------------------------------------------
extern "C" void kernel_launch(void* const* d_in, const int* in_sizes, int n_in,
                              void* d_out, int out_size) {
    const float* x = (const float*)d_in[0];
    const int* idx = (const int*)d_in[1];
    float* out = (float*)d_out;

    cudaFuncSetAttribute(score_mma, cudaFuncAttributeMaxDynamicSharedMemorySize, TC_SMEM);
    cudaFuncSetAttribute(recon_mma, cudaFuncAttributeMaxDynamicSharedMemorySize, TC_SMEM);

    zero_colsum_kernel<<<1, KA>>>();
    norm_kernel<<<ROWS / 256, 256>>>(x);
    xt_kernel<<<dim3(HW / 32, CD / 32, NB), dim3(32, 8)>>>(x);
    gather_cj<<<(NB * CD * KA) / 256, 256>>>(x, idx);
    gather_jc<<<(NB * KA * CD) / 256, 256>>>(x, idx);

    score_mma<<<dim3(HW / 128, KA / 128, NB), 256, TC_SMEM>>>();   // A0(fp16) + colsum0

    recip_kernel<<<1, KA>>>();                       // c1
    for (int it = 0; it < 3; ++it) {
        sk_pass<<<ROWS / 128, 256>>>();
        recip_kernel<<<1, KA>>>();                   // c2, c3, c4
    }
    recon_mma<<<dim3(HW / 128, CD / 128, NB), 256, TC_SMEM>>>(out);
}

// round 7
// speedup vs baseline: 1.5381x; 1.2021x over previous
#include <cuda_runtime.h>
#include <cuda_bf16.h>
#include <cuda_fp16.h>
#include <cstdint>

#define NB 16
#define CD 256
#define HW 4096
#define KA 512
#define ROWS (NB*HW)   // 65536

// ---------------- scratch (__device__ globals; no allocations) ----------------
__device__ __align__(16) __half g_A0[(size_t)ROWS * KA];             // 64 MB (fp16)
__device__ __align__(16) __half g_Xf[(size_t)ROWS * CD];             // X^T fp16 [n][hw][c]
__device__ __align__(16) __half g_Sfj[(size_t)NB*KA*CD];             // S fp16 [n][j][c]
__device__ __align__(16) __nv_bfloat16 g_Shc[(size_t)NB*CD*KA];      // S hi [n][c][j]
__device__ __align__(16) __nv_bfloat16 g_Slc[(size_t)NB*CD*KA];      // S lo [n][c][j]
__device__ float g_invnorm[ROWS];
__device__ float g_colsum[KA];
__device__ float g_cvec[KA];

// ---------------- helpers ----------------
__device__ __forceinline__ uint32_t smem_u32(const void* p) {
    uint32_t a;
    asm("{ .reg .u64 t; cvta.to.shared.u64 t, %1; cvt.u32.u64 %0, t; }" : "=r"(a) : "l"(p));
    return a;
}
__device__ __forceinline__ uint32_t swz(uint32_t o) { return o ^ ((o >> 3) & 0x70); }
__device__ __forceinline__ uint32_t pack_bf2(__nv_bfloat16 a, __nv_bfloat16 b) {
    return (uint32_t)__bfloat16_as_ushort(a) | ((uint32_t)__bfloat16_as_ushort(b) << 16);
}
__device__ __forceinline__ void split_bf(float f, __nv_bfloat16& h, __nv_bfloat16& l) {
    h = __float2bfloat16(f);
    l = __float2bfloat16(f - __bfloat162float(h));
}
__device__ __forceinline__ void ldm4(uint32_t addr, uint32_t r[4]) {
    asm volatile("ldmatrix.sync.aligned.m8n8.x4.shared.b16 {%0,%1,%2,%3}, [%4];"
        : "=r"(r[0]), "=r"(r[1]), "=r"(r[2]), "=r"(r[3]) : "r"(addr));
}
__device__ __forceinline__ void mma_bf(float c[4], const uint32_t a[4],
                                       uint32_t b0, uint32_t b1) {
    asm volatile("mma.sync.aligned.m16n8k16.row.col.f32.bf16.bf16.f32 "
        "{%0,%1,%2,%3}, {%4,%5,%6,%7}, {%8,%9}, {%0,%1,%2,%3};"
        : "+f"(c[0]), "+f"(c[1]), "+f"(c[2]), "+f"(c[3])
        : "r"(a[0]), "r"(a[1]), "r"(a[2]), "r"(a[3]), "r"(b0), "r"(b1));
}
__device__ __forceinline__ void mma_hf(float c[4], const uint32_t a[4],
                                       uint32_t b0, uint32_t b1) {
    asm volatile("mma.sync.aligned.m16n8k16.row.col.f32.f16.f16.f32 "
        "{%0,%1,%2,%3}, {%4,%5,%6,%7}, {%8,%9}, {%0,%1,%2,%3};"
        : "+f"(c[0]), "+f"(c[1]), "+f"(c[2]), "+f"(c[3])
        : "r"(a[0]), "r"(a[1]), "r"(a[2]), "r"(a[3]), "r"(b0), "r"(b1));
}
__device__ __forceinline__ uint32_t afrag_addr(uint32_t base, int mbase, int s, int lane) {
    int row = mbase + (lane & 7) + ((lane >> 3) & 1) * 8;
    int unit = 2 * s + (lane >> 4);
    return base + swz((uint32_t)(row * 128 + unit * 16));
}
__device__ __forceinline__ uint32_t bfrag_addr(uint32_t base, int nbase, int s, int lane) {
    int row = nbase + (lane & 7) + ((lane >> 4) & 1) * 8;
    int unit = 2 * s + ((lane >> 3) & 1);
    return base + swz((uint32_t)(row * 128 + unit * 16));
}

// SMEM layouts
// score: colred 512B | AF @4096 (16KB) | BF @20480 (16KB)  -> 36KB, 2+ CTA/SM
#define S_AF 4096
#define S_BF 20480
#define SC_SMEM 36864
// recon: red 512B | cvec @512 (2KB) | AH/AL/BH/BL 4x16KB @4096 -> 68KB, 2 CTA/SM
#define OFF_CV   512
#define OFF_AH   4096
#define OFF_AL   (4096 + 16384)
#define OFF_BH   (4096 + 32768)
#define OFF_BL   (4096 + 49152)
#define RC_SMEM  (4096 + 65536)

// ---------------- small kernels ----------------
__global__ void zero_colsum_kernel() { g_colsum[threadIdx.x] = 0.0f; }

__global__ void norm_kernel(const float* __restrict__ x) {
    int i = blockIdx.x * blockDim.x + threadIdx.x;
    int n = i >> 12, hw = i & 4095;
    const float* p = x + (size_t)n * CD * HW + hw;
    float acc = 0.0f;
#pragma unroll 16
    for (int c = 0; c < CD; ++c) { float v = p[(size_t)c * HW]; acc = fmaf(v, v, acc); }
    g_invnorm[i] = 1.0f / fmaxf(sqrtf(acc), 1e-12f);
}

// transpose x[n][c][hw] -> Xf fp16 [n][hw][c]
__global__ void xt_kernel(const float* __restrict__ x) {
    __shared__ float t[32][33];
    int n = blockIdx.z, hw0 = blockIdx.x * 32, c0 = blockIdx.y * 32;
    int tx = threadIdx.x, ty = threadIdx.y;
#pragma unroll
    for (int r = 0; r < 32; r += 8)
        t[ty + r][tx] = x[((size_t)n * CD + c0 + ty + r) * HW + hw0 + tx];
    __syncthreads();
#pragma unroll
    for (int r = 0; r < 32; r += 8) {
        float v = t[tx][ty + r];
        g_Xf[((size_t)n * HW + hw0 + ty + r) * CD + c0 + tx] = __float2half(v);
    }
}

__global__ void gather_cj(const float* __restrict__ x, const int* __restrict__ idx) {
    int t = blockIdx.x * blockDim.x + threadIdx.x;   // [n][c][j], j fastest
    int j = t & (KA - 1);
    int nc = t >> 9;
    int n = nc >> 8;
    int pos = idx[j];
    float v = x[(size_t)nc * HW + pos] * g_invnorm[n * HW + pos];
    __nv_bfloat16 h, l; split_bf(v, h, l);
    g_Shc[t] = h; g_Slc[t] = l;
}
__global__ void gather_jc(const float* __restrict__ x, const int* __restrict__ idx) {
    int t = blockIdx.x * blockDim.x + threadIdx.x;   // [n][j][c], c fastest
    int c = t & (CD - 1);
    int nj = t >> 8;
    int j = nj & (KA - 1);
    int n = nj >> 9;
    int pos = idx[j];
    float v = x[((size_t)n * CD + c) * HW + pos] * g_invnorm[n * HW + pos];
    g_Sfj[t] = __float2half(v);
}

__global__ void recip_kernel() {
    int j = threadIdx.x;
    g_cvec[j] = 1.0f / fmaxf(g_colsum[j], 1e-30f);
    g_colsum[j] = 0.0f;
}

// fused Sinkhorn pass on fp16 A0
__global__ __launch_bounds__(256) void sk_pass() {
    __shared__ float cred[KA];
    int tid = threadIdx.x;
    cred[tid] = 0.0f; cred[tid + 256] = 0.0f;
    __syncthreads();
    int warp = tid >> 5, lane = tid & 31;
    float cv[16];
#pragma unroll
    for (int e = 0; e < 8; ++e) { cv[e] = g_cvec[lane * 8 + e]; cv[8 + e] = g_cvec[256 + lane * 8 + e]; }
    float ca[16];
#pragma unroll
    for (int e = 0; e < 16; ++e) ca[e] = 0.0f;
    size_t rbase = (size_t)blockIdx.x * 128 + warp * 16;
    for (int t = 0; t < 16; ++t) {
        const uint4* row = (const uint4*)(g_A0 + (rbase + t) * KA);
        uint4 u0 = row[lane], u1 = row[lane + 32];
        float a[16];
        {
            const __half2* h0 = (const __half2*)&u0;
            const __half2* h1 = (const __half2*)&u1;
#pragma unroll
            for (int k = 0; k < 4; ++k) {
                float2 f0 = __half22float2(h0[k]);
                float2 f1 = __half22float2(h1[k]);
                a[2*k] = f0.x; a[2*k+1] = f0.y;
                a[8 + 2*k] = f1.x; a[8 + 2*k+1] = f1.y;
            }
        }
        float d = 0.0f;
#pragma unroll
        for (int e = 0; e < 16; ++e) d = fmaf(a[e], cv[e], d);
#pragma unroll
        for (int s = 16; s > 0; s >>= 1) d += __shfl_xor_sync(0xffffffffu, d, s);
        float r = 1.0f / fmaxf(d, 1e-30f);
#pragma unroll
        for (int e = 0; e < 16; ++e) ca[e] = fmaf(r, a[e], ca[e]);
    }
#pragma unroll
    for (int e = 0; e < 8; ++e) {
        atomicAdd(&cred[lane * 8 + e], ca[e]);
        atomicAdd(&cred[256 + lane * 8 + e], ca[8 + e]);
    }
    __syncthreads();
    atomicAdd(&g_colsum[tid], cred[tid]);
    atomicAdd(&g_colsum[tid + 256], cred[tid + 256]);
}

// ================= score GEMM: single fp16 mma + fused colsum + fp16 A0 =================
__global__ __launch_bounds__(256, 2) void score_mma() {
    extern __shared__ char smem[];
    uint32_t sb = smem_u32(smem);
    float* colred = (float*)smem;
    int tid = threadIdx.x, lane = tid & 31, w = tid >> 5;
    int n = blockIdx.z, hw0 = blockIdx.x * 128, j0 = blockIdx.y * 128;
    int wm = (w & 3) * 32, wn = (w >> 2) * 64;

    float acc[2][8][4];
#pragma unroll
    for (int a = 0; a < 2; ++a)
#pragma unroll
        for (int b = 0; b < 8; ++b)
#pragma unroll
            for (int c = 0; c < 4; ++c) acc[a][b][c] = 0.0f;

    int crow = tid >> 1, chalf = tid & 1;
    const uint4* aF = (const uint4*)(g_Xf + ((size_t)n * HW + hw0 + crow) * CD);
    const uint4* bF = (const uint4*)(g_Sfj + ((size_t)n * KA + j0 + crow) * CD);

    for (int ch = 0; ch < 4; ++ch) {
#pragma unroll
        for (int q = 0; q < 4; ++q) {
            int unit = chalf * 4 + q;
            uint32_t off = swz((uint32_t)(crow * 128 + unit * 16));
            int gi = ch * 8 + unit;
            *(uint4*)(smem + S_AF + off) = aF[gi];
            *(uint4*)(smem + S_BF + off) = bF[gi];
        }
        __syncthreads();
#pragma unroll
        for (int s = 0; s < 4; ++s) {
            uint32_t af[2][4];
#pragma unroll
            for (int mt = 0; mt < 2; ++mt)
                ldm4(afrag_addr(sb + S_AF, wm + mt * 16, s, lane), af[mt]);
#pragma unroll
            for (int ng = 0; ng < 4; ++ng) {
                uint32_t bf[4];
                ldm4(bfrag_addr(sb + S_BF, wn + ng * 16, s, lane), bf);
                mma_hf(acc[0][2*ng],   af[0], bf[0], bf[1]);
                mma_hf(acc[1][2*ng],   af[1], bf[0], bf[1]);
                mma_hf(acc[0][2*ng+1], af[0], bf[2], bf[3]);
                mma_hf(acc[1][2*ng+1], af[1], bf[2], bf[3]);
            }
        }
        __syncthreads();
    }

    // epilogue: exp -> fp16 store + fused first column-sum (from rounded values)
    if (tid < 128) colred[tid] = 0.0f;
    __syncthreads();
    float colp[16];
#pragma unroll
    for (int e = 0; e < 16; ++e) colp[e] = 0.0f;
#pragma unroll
    for (int mt = 0; mt < 2; ++mt) {
        int i0 = n * HW + hw0 + wm + mt * 16 + (lane >> 2);
        int i1 = i0 + 8;
        float s0 = g_invnorm[i0] * (1.0f / 0.3f);
        float s1 = g_invnorm[i1] * (1.0f / 0.3f);
        __half* r0 = g_A0 + (size_t)i0 * KA + j0 + wn + (lane & 3) * 2;
        __half* r1 = g_A0 + (size_t)i1 * KA + j0 + wn + (lane & 3) * 2;
#pragma unroll
        for (int nt = 0; nt < 8; ++nt) {
            __half h0 = __float2half(__expf(acc[mt][nt][0] * s0));
            __half h1 = __float2half(__expf(acc[mt][nt][1] * s0));
            __half h2 = __float2half(__expf(acc[mt][nt][2] * s1));
            __half h3 = __float2half(__expf(acc[mt][nt][3] * s1));
            *(__half2*)(r0 + nt * 8) = __halves2half2(h0, h1);
            *(__half2*)(r1 + nt * 8) = __halves2half2(h2, h3);
            colp[nt * 2]     += __half2float(h0) + __half2float(h2);
            colp[nt * 2 + 1] += __half2float(h1) + __half2float(h3);
        }
    }
#pragma unroll
    for (int nt = 0; nt < 8; ++nt) {
        int cl = wn + (lane & 3) * 2 + nt * 8;
        atomicAdd(&colred[cl], colp[nt * 2]);
        atomicAdd(&colred[cl + 1], colp[nt * 2 + 1]);
    }
    __syncthreads();
    if (tid < 128) atomicAdd(&g_colsum[j0 + tid], colred[tid]);
}

// ================= reconstruct GEMM (bf16 hi/lo, fp16 A0 loads) =================
__global__ __launch_bounds__(256, 2) void recon_mma(float* __restrict__ out) {
    extern __shared__ char smem[];
    uint32_t sb = smem_u32(smem);
    float* red = (float*)smem;
    float* cs  = (float*)(smem + OFF_CV);
    int tid = threadIdx.x, lane = tid & 31, w = tid >> 5;
    int n = blockIdx.z, hw0 = blockIdx.x * 128, c0 = blockIdx.y * 128;
    int wm = (w & 3) * 32, wn = (w >> 2) * 64;

    if (tid < 128) red[tid] = 0.0f;
    cs[tid] = g_cvec[tid];
    cs[256 + tid] = g_cvec[256 + tid];

    float acc[2][8][4];
#pragma unroll
    for (int a = 0; a < 2; ++a)
#pragma unroll
        for (int b = 0; b < 8; ++b)
#pragma unroll
            for (int c = 0; c < 4; ++c) acc[a][b][c] = 0.0f;

    int crow = tid >> 1, chalf = tid & 1;
    const uint4* aH = (const uint4*)(g_Shc + ((size_t)n * CD + c0 + crow) * KA);
    const uint4* aL = (const uint4*)(g_Slc + ((size_t)n * CD + c0 + crow) * KA);
    const uint4* arow4 = (const uint4*)(g_A0 + ((size_t)(n * HW + hw0 + crow)) * KA);
    __syncthreads();

    for (int ch = 0; ch < 8; ++ch) {
        int k0 = ch * 64;
#pragma unroll
        for (int q = 0; q < 4; ++q) {
            int unit = chalf * 4 + q;
            uint32_t off = swz((uint32_t)(crow * 128 + unit * 16));
            int gi = ch * 8 + unit;
            *(uint4*)(smem + OFF_AH + off) = aH[gi];
            *(uint4*)(smem + OFF_AL + off) = aL[gi];
        }
        {
            float dp = 0.0f;
#pragma unroll
            for (int q = 0; q < 4; ++q) {
                uint4 u = arow4[ch * 8 + chalf * 4 + q];
                const __half2* hp = (const __half2*)&u;
                int jb = k0 + (chalf * 4 + q) * 8;
                float v[8];
#pragma unroll
                for (int k = 0; k < 4; ++k) {
                    float2 f = __half22float2(hp[k]);
                    v[2*k]   = f.x * cs[jb + 2*k];
                    v[2*k+1] = f.y * cs[jb + 2*k+1];
                }
                dp += v[0]+v[1]+v[2]+v[3]+v[4]+v[5]+v[6]+v[7];
                __nv_bfloat16 h[8], l[8];
#pragma unroll
                for (int k = 0; k < 8; ++k) split_bf(v[k], h[k], l[k]);
                uint32_t off = swz((uint32_t)(crow * 128 + (chalf * 4 + q) * 16));
                *(uint4*)(smem + OFF_BH + off) =
                    make_uint4(pack_bf2(h[0],h[1]), pack_bf2(h[2],h[3]),
                               pack_bf2(h[4],h[5]), pack_bf2(h[6],h[7]));
                *(uint4*)(smem + OFF_BL + off) =
                    make_uint4(pack_bf2(l[0],l[1]), pack_bf2(l[2],l[3]),
                               pack_bf2(l[4],l[5]), pack_bf2(l[6],l[7]));
            }
            atomicAdd(&red[crow], dp);
        }
        __syncthreads();
#pragma unroll
        for (int s = 0; s < 4; ++s) {
            uint32_t ah[2][4], al[2][4];
#pragma unroll
            for (int mt = 0; mt < 2; ++mt) {
                ldm4(afrag_addr(sb + OFF_AH, wm + mt * 16, s, lane), ah[mt]);
                ldm4(afrag_addr(sb + OFF_AL, wm + mt * 16, s, lane), al[mt]);
            }
#pragma unroll
            for (int ng = 0; ng < 4; ++ng) {
                uint32_t bh[4], bl[4];
                ldm4(bfrag_addr(sb + OFF_BH, wn + ng * 16, s, lane), bh);
                ldm4(bfrag_addr(sb + OFF_BL, wn + ng * 16, s, lane), bl);
                mma_bf(acc[0][2*ng],   ah[0], bh[0], bh[1]);
                mma_bf(acc[1][2*ng],   ah[1], bh[0], bh[1]);
                mma_bf(acc[0][2*ng+1], ah[0], bh[2], bh[3]);
                mma_bf(acc[1][2*ng+1], ah[1], bh[2], bh[3]);
                mma_bf(acc[0][2*ng],   ah[0], bl[0], bl[1]);
                mma_bf(acc[1][2*ng],   ah[1], bl[0], bl[1]);
                mma_bf(acc[0][2*ng+1], ah[0], bl[2], bl[3]);
                mma_bf(acc[1][2*ng+1], ah[1], bl[2], bl[3]);
                mma_bf(acc[0][2*ng],   al[0], bh[0], bh[1]);
                mma_bf(acc[1][2*ng],   al[1], bh[0], bh[1]);
                mma_bf(acc[0][2*ng+1], al[0], bh[2], bh[3]);
                mma_bf(acc[1][2*ng+1], al[1], bh[2], bh[3]);
            }
        }
        __syncthreads();
    }

    if (tid < 128) red[tid] = 1.0f / fmaxf(red[tid], 1e-30f);
    __syncthreads();

#pragma unroll
    for (int mt = 0; mt < 2; ++mt) {
        int c = c0 + wm + mt * 16 + (lane >> 2);
        int nl = wn + (lane & 3) * 2;
        float* o0 = out + ((size_t)n * CD + c) * HW + hw0 + nl;
        float* o1 = out + ((size_t)n * CD + c + 8) * HW + hw0 + nl;
#pragma unroll
        for (int nt = 0; nt < 8; ++nt) {
            float rx = red[nl + nt * 8], ry = red[nl + nt * 8 + 1];
            *(float2*)(o0 + nt * 8) = make_float2(acc[mt][nt][0] * rx, acc[mt][nt][1] * ry);
            *(float2*)(o1 + nt * 8) = make_float2(acc[mt][nt][2] * rx, acc[mt][nt][3] * ry);
        }
    }
}

// ----------------------------------------------------------------
extern "C" void kernel_launch(void* const* d_in, const int* in_sizes, int n_in,
                              void* d_out, int out_size) {
    const float* x = (const float*)d_in[0];
    const int* idx = (const int*)d_in[1];
    float* out = (float*)d_out;

    cudaFuncSetAttribute(score_mma, cudaFuncAttributeMaxDynamicSharedMemorySize, SC_SMEM);
    cudaFuncSetAttribute(recon_mma, cudaFuncAttributeMaxDynamicSharedMemorySize, RC_SMEM);

    zero_colsum_kernel<<<1, KA>>>();
    norm_kernel<<<ROWS / 256, 256>>>(x);
    xt_kernel<<<dim3(HW / 32, CD / 32, NB), dim3(32, 8)>>>(x);
    gather_cj<<<(NB * CD * KA) / 256, 256>>>(x, idx);
    gather_jc<<<(NB * KA * CD) / 256, 256>>>(x, idx);

    score_mma<<<dim3(HW / 128, KA / 128, NB), 256, SC_SMEM>>>();   // A0(fp16) + colsum0

    recip_kernel<<<1, KA>>>();                       // c1
    for (int it = 0; it < 3; ++it) {
        sk_pass<<<ROWS / 128, 256>>>();
        recip_kernel<<<1, KA>>>();                   // c2, c3, c4
    }
    recon_mma<<<dim3(HW / 128, CD / 128, NB), 256, RC_SMEM>>>(out);
}

// round 8
// speedup vs baseline: 1.7674x; 1.1491x over previous
#include <cuda_runtime.h>
#include <cuda_bf16.h>
#include <cuda_fp16.h>
#include <cstdint>

#define NB 16
#define CD 256
#define HW 4096
#define KA 512
#define ROWS (NB*HW)   // 65536

// ---------------- scratch (__device__ globals; no allocations) ----------------
__device__ __align__(16) __half g_A0[(size_t)ROWS * KA];             // 64 MB (fp16)
__device__ __align__(16) __half g_Xf[(size_t)ROWS * CD];             // X^T fp16 [n][hw][c]
__device__ __align__(16) __half g_Sfj[(size_t)NB*KA*CD];             // S fp16 [n][j][c]
__device__ __align__(16) float  g_Scf[(size_t)NB*CD*KA];             // S fp32 [n][c][j]
__device__ __align__(16) __half g_Sck[(size_t)NB*CD*KA];             // S*c fp16 [n][c][j]
__device__ float g_invnorm[ROWS];
__device__ float g_dinv[ROWS];
__device__ float g_colsum[KA];
__device__ float g_cvec[KA];

// ---------------- helpers ----------------
__device__ __forceinline__ uint32_t smem_u32(const void* p) {
    uint32_t a;
    asm("{ .reg .u64 t; cvta.to.shared.u64 t, %1; cvt.u32.u64 %0, t; }" : "=r"(a) : "l"(p));
    return a;
}
__device__ __forceinline__ uint32_t swz(uint32_t o) { return o ^ ((o >> 3) & 0x70); }
__device__ __forceinline__ void ldm4(uint32_t addr, uint32_t r[4]) {
    asm volatile("ldmatrix.sync.aligned.m8n8.x4.shared.b16 {%0,%1,%2,%3}, [%4];"
        : "=r"(r[0]), "=r"(r[1]), "=r"(r[2]), "=r"(r[3]) : "r"(addr));
}
__device__ __forceinline__ void mma_hf(float c[4], const uint32_t a[4],
                                       uint32_t b0, uint32_t b1) {
    asm volatile("mma.sync.aligned.m16n8k16.row.col.f32.f16.f16.f32 "
        "{%0,%1,%2,%3}, {%4,%5,%6,%7}, {%8,%9}, {%0,%1,%2,%3};"
        : "+f"(c[0]), "+f"(c[1]), "+f"(c[2]), "+f"(c[3])
        : "r"(a[0]), "r"(a[1]), "r"(a[2]), "r"(a[3]), "r"(b0), "r"(b1));
}
__device__ __forceinline__ uint32_t afrag_addr(uint32_t base, int mbase, int s, int lane) {
    int row = mbase + (lane & 7) + ((lane >> 3) & 1) * 8;
    int unit = 2 * s + (lane >> 4);
    return base + swz((uint32_t)(row * 128 + unit * 16));
}
__device__ __forceinline__ uint32_t bfrag_addr(uint32_t base, int nbase, int s, int lane) {
    int row = nbase + (lane & 7) + ((lane >> 4) & 1) * 8;
    int unit = 2 * s + ((lane >> 3) & 1);
    return base + swz((uint32_t)(row * 128 + unit * 16));
}

// SMEM layouts: red 512B | AF @4096 (16KB) | BF @20480 (16KB) -> 36KB
#define S_AF 4096
#define S_BF 20480
#define SC_SMEM 36864

// ---------------- small kernels ----------------
__global__ void zero_colsum_kernel() { g_colsum[threadIdx.x] = 0.0f; }

__global__ void norm_kernel(const float* __restrict__ x) {
    int i = blockIdx.x * blockDim.x + threadIdx.x;
    int n = i >> 12, hw = i & 4095;
    const float* p = x + (size_t)n * CD * HW + hw;
    float acc = 0.0f;
#pragma unroll 16
    for (int c = 0; c < CD; ++c) { float v = p[(size_t)c * HW]; acc = fmaf(v, v, acc); }
    g_invnorm[i] = 1.0f / fmaxf(sqrtf(acc), 1e-12f);
}

// transpose x[n][c][hw] -> Xf fp16 [n][hw][c]
__global__ void xt_kernel(const float* __restrict__ x) {
    __shared__ float t[32][33];
    int n = blockIdx.z, hw0 = blockIdx.x * 32, c0 = blockIdx.y * 32;
    int tx = threadIdx.x, ty = threadIdx.y;
#pragma unroll
    for (int r = 0; r < 32; r += 8)
        t[ty + r][tx] = x[((size_t)n * CD + c0 + ty + r) * HW + hw0 + tx];
    __syncthreads();
#pragma unroll
    for (int r = 0; r < 32; r += 8) {
        float v = t[tx][ty + r];
        g_Xf[((size_t)n * HW + hw0 + ty + r) * CD + c0 + tx] = __float2half(v);
    }
}

__global__ void gather_cj(const float* __restrict__ x, const int* __restrict__ idx) {
    int t = blockIdx.x * blockDim.x + threadIdx.x;   // [n][c][j], j fastest
    int j = t & (KA - 1);
    int nc = t >> 9;
    int n = nc >> 8;
    int pos = idx[j];
    g_Scf[t] = x[(size_t)nc * HW + pos] * g_invnorm[n * HW + pos];
}
__global__ void gather_jc(const float* __restrict__ x, const int* __restrict__ idx) {
    int t = blockIdx.x * blockDim.x + threadIdx.x;   // [n][j][c], c fastest
    int c = t & (CD - 1);
    int nj = t >> 8;
    int j = nj & (KA - 1);
    int n = nj >> 9;
    int pos = idx[j];
    g_Sfj[t] = __float2half(x[((size_t)n * CD + c) * HW + pos] * g_invnorm[n * HW + pos]);
}

// c = (1/colsum) normalized by its max (output scale-invariant); reset colsum
__global__ void recip_kernel() {
    __shared__ float sm[KA];
    int j = threadIdx.x;
    float c = 1.0f / fmaxf(g_colsum[j], 1e-30f);
    sm[j] = c;
    __syncthreads();
    for (int s = 256; s > 0; s >>= 1) {
        if (j < s) sm[j] = fmaxf(sm[j], sm[j + s]);
        __syncthreads();
    }
    g_cvec[j] = c / sm[0];
    g_colsum[j] = 0.0f;
}

// S' = fp16(S_float * c)  [n][c][j]
__global__ void scale_s_kernel() {
    int t = blockIdx.x * blockDim.x + threadIdx.x;
    int j = t & (KA - 1);
    g_Sck[t] = __float2half(g_Scf[t] * g_cvec[j]);
}

// dinv_i = 1 / (A0_i . c)
__global__ __launch_bounds__(256) void dinv_kernel() {
    int tid = threadIdx.x;
    int warp = tid >> 5, lane = tid & 31;
    float cv[16];
#pragma unroll
    for (int e = 0; e < 8; ++e) { cv[e] = g_cvec[lane * 8 + e]; cv[8 + e] = g_cvec[256 + lane * 8 + e]; }
    size_t rbase = (size_t)blockIdx.x * 128 + warp * 16;
    for (int t = 0; t < 16; ++t) {
        const uint4* row = (const uint4*)(g_A0 + (rbase + t) * KA);
        uint4 u0 = row[lane], u1 = row[lane + 32];
        const __half2* h0 = (const __half2*)&u0;
        const __half2* h1 = (const __half2*)&u1;
        float d = 0.0f;
#pragma unroll
        for (int k = 0; k < 4; ++k) {
            float2 f0 = __half22float2(h0[k]);
            float2 f1 = __half22float2(h1[k]);
            d = fmaf(f0.x, cv[2*k], d);   d = fmaf(f0.y, cv[2*k+1], d);
            d = fmaf(f1.x, cv[8+2*k], d); d = fmaf(f1.y, cv[8+2*k+1], d);
        }
#pragma unroll
        for (int s = 16; s > 0; s >>= 1) d += __shfl_xor_sync(0xffffffffu, d, s);
        if (lane == 0) g_dinv[rbase + t] = 1.0f / fmaxf(d, 1e-30f);
    }
}

// fused Sinkhorn pass on fp16 A0
__global__ __launch_bounds__(256) void sk_pass() {
    __shared__ float cred[KA];
    int tid = threadIdx.x;
    cred[tid] = 0.0f; cred[tid + 256] = 0.0f;
    __syncthreads();
    int warp = tid >> 5, lane = tid & 31;
    float cv[16];
#pragma unroll
    for (int e = 0; e < 8; ++e) { cv[e] = g_cvec[lane * 8 + e]; cv[8 + e] = g_cvec[256 + lane * 8 + e]; }
    float ca[16];
#pragma unroll
    for (int e = 0; e < 16; ++e) ca[e] = 0.0f;
    size_t rbase = (size_t)blockIdx.x * 128 + warp * 16;
    for (int t = 0; t < 16; ++t) {
        const uint4* row = (const uint4*)(g_A0 + (rbase + t) * KA);
        uint4 u0 = row[lane], u1 = row[lane + 32];
        float a[16];
        {
            const __half2* h0 = (const __half2*)&u0;
            const __half2* h1 = (const __half2*)&u1;
#pragma unroll
            for (int k = 0; k < 4; ++k) {
                float2 f0 = __half22float2(h0[k]);
                float2 f1 = __half22float2(h1[k]);
                a[2*k] = f0.x; a[2*k+1] = f0.y;
                a[8 + 2*k] = f1.x; a[8 + 2*k+1] = f1.y;
            }
        }
        float d = 0.0f;
#pragma unroll
        for (int e = 0; e < 16; ++e) d = fmaf(a[e], cv[e], d);
#pragma unroll
        for (int s = 16; s > 0; s >>= 1) d += __shfl_xor_sync(0xffffffffu, d, s);
        float r = 1.0f / fmaxf(d, 1e-30f);
#pragma unroll
        for (int e = 0; e < 16; ++e) ca[e] = fmaf(r, a[e], ca[e]);
    }
#pragma unroll
    for (int e = 0; e < 8; ++e) {
        atomicAdd(&cred[lane * 8 + e], ca[e]);
        atomicAdd(&cred[256 + lane * 8 + e], ca[8 + e]);
    }
    __syncthreads();
    atomicAdd(&g_colsum[tid], cred[tid]);
    atomicAdd(&g_colsum[tid + 256], cred[tid + 256]);
}

// ================= score GEMM: single fp16 mma + fused colsum + fp16 A0 =================
__global__ __launch_bounds__(256, 2) void score_mma() {
    extern __shared__ char smem[];
    uint32_t sb = smem_u32(smem);
    float* colred = (float*)smem;
    int tid = threadIdx.x, lane = tid & 31, w = tid >> 5;
    int n = blockIdx.z, hw0 = blockIdx.x * 128, j0 = blockIdx.y * 128;
    int wm = (w & 3) * 32, wn = (w >> 2) * 64;

    float acc[2][8][4];
#pragma unroll
    for (int a = 0; a < 2; ++a)
#pragma unroll
        for (int b = 0; b < 8; ++b)
#pragma unroll
            for (int c = 0; c < 4; ++c) acc[a][b][c] = 0.0f;

    int crow = tid >> 1, chalf = tid & 1;
    const uint4* aF = (const uint4*)(g_Xf + ((size_t)n * HW + hw0 + crow) * CD);
    const uint4* bF = (const uint4*)(g_Sfj + ((size_t)n * KA + j0 + crow) * CD);

    for (int ch = 0; ch < 4; ++ch) {
#pragma unroll
        for (int q = 0; q < 4; ++q) {
            int unit = chalf * 4 + q;
            uint32_t off = swz((uint32_t)(crow * 128 + unit * 16));
            int gi = ch * 8 + unit;
            *(uint4*)(smem + S_AF + off) = aF[gi];
            *(uint4*)(smem + S_BF + off) = bF[gi];
        }
        __syncthreads();
#pragma unroll
        for (int s = 0; s < 4; ++s) {
            uint32_t af[2][4];
#pragma unroll
            for (int mt = 0; mt < 2; ++mt)
                ldm4(afrag_addr(sb + S_AF, wm + mt * 16, s, lane), af[mt]);
#pragma unroll
            for (int ng = 0; ng < 4; ++ng) {
                uint32_t bf[4];
                ldm4(bfrag_addr(sb + S_BF, wn + ng * 16, s, lane), bf);
                mma_hf(acc[0][2*ng],   af[0], bf[0], bf[1]);
                mma_hf(acc[1][2*ng],   af[1], bf[0], bf[1]);
                mma_hf(acc[0][2*ng+1], af[0], bf[2], bf[3]);
                mma_hf(acc[1][2*ng+1], af[1], bf[2], bf[3]);
            }
        }
        __syncthreads();
    }

    // epilogue: exp -> fp16 store + fused first column-sum (from rounded values)
    if (tid < 128) colred[tid] = 0.0f;
    __syncthreads();
    float colp[16];
#pragma unroll
    for (int e = 0; e < 16; ++e) colp[e] = 0.0f;
#pragma unroll
    for (int mt = 0; mt < 2; ++mt) {
        int i0 = n * HW + hw0 + wm + mt * 16 + (lane >> 2);
        int i1 = i0 + 8;
        float s0 = g_invnorm[i0] * (1.0f / 0.3f);
        float s1 = g_invnorm[i1] * (1.0f / 0.3f);
        __half* r0 = g_A0 + (size_t)i0 * KA + j0 + wn + (lane & 3) * 2;
        __half* r1 = g_A0 + (size_t)i1 * KA + j0 + wn + (lane & 3) * 2;
#pragma unroll
        for (int nt = 0; nt < 8; ++nt) {
            __half h0 = __float2half(__expf(acc[mt][nt][0] * s0));
            __half h1 = __float2half(__expf(acc[mt][nt][1] * s0));
            __half h2 = __float2half(__expf(acc[mt][nt][2] * s1));
            __half h3 = __float2half(__expf(acc[mt][nt][3] * s1));
            *(__half2*)(r0 + nt * 8) = __halves2half2(h0, h1);
            *(__half2*)(r1 + nt * 8) = __halves2half2(h2, h3);
            colp[nt * 2]     += __half2float(h0) + __half2float(h2);
            colp[nt * 2 + 1] += __half2float(h1) + __half2float(h3);
        }
    }
#pragma unroll
    for (int nt = 0; nt < 8; ++nt) {
        int cl = wn + (lane & 3) * 2 + nt * 8;
        atomicAdd(&colred[cl], colp[nt * 2]);
        atomicAdd(&colred[cl + 1], colp[nt * 2 + 1]);
    }
    __syncthreads();
    if (tid < 128) atomicAdd(&g_colsum[j0 + tid], colred[tid]);
}

// ================= reconstruct GEMM: single fp16 mma, pure-copy loaders =================
// out[n][c0+m][hw0+nn] = dinv_nn * sum_j S'[m][j] * A0[nn][j]
// M=128(c) N=128(hw) K=512(j) in 8 chunks of 64. A = S*c fp16, B = raw A0 fp16.
__global__ __launch_bounds__(256, 2) void recon_mma(float* __restrict__ out) {
    extern __shared__ char smem[];
    uint32_t sb = smem_u32(smem);
    float* ds = (float*)smem;   // 128 floats: dinv for this hw tile
    int tid = threadIdx.x, lane = tid & 31, w = tid >> 5;
    int n = blockIdx.z, hw0 = blockIdx.x * 128, c0 = blockIdx.y * 128;
    int wm = (w & 3) * 32, wn = (w >> 2) * 64;

    if (tid < 128) ds[tid] = g_dinv[n * HW + hw0 + tid];

    float acc[2][8][4];
#pragma unroll
    for (int a = 0; a < 2; ++a)
#pragma unroll
        for (int b = 0; b < 8; ++b)
#pragma unroll
            for (int c = 0; c < 4; ++c) acc[a][b][c] = 0.0f;

    int crow = tid >> 1, chalf = tid & 1;
    const uint4* aF = (const uint4*)(g_Sck + ((size_t)n * CD + c0 + crow) * KA);
    const uint4* bF = (const uint4*)(g_A0 + ((size_t)(n * HW + hw0 + crow)) * KA);

    for (int ch = 0; ch < 8; ++ch) {
#pragma unroll
        for (int q = 0; q < 4; ++q) {
            int unit = chalf * 4 + q;
            uint32_t off = swz((uint32_t)(crow * 128 + unit * 16));
            int gi = ch * 8 + unit;
            *(uint4*)(smem + S_AF + off) = aF[gi];
            *(uint4*)(smem + S_BF + off) = bF[gi];
        }
        __syncthreads();
#pragma unroll
        for (int s = 0; s < 4; ++s) {
            uint32_t af[2][4];
#pragma unroll
            for (int mt = 0; mt < 2; ++mt)
                ldm4(afrag_addr(sb + S_AF, wm + mt * 16, s, lane), af[mt]);
#pragma unroll
            for (int ng = 0; ng < 4; ++ng) {
                uint32_t bf[4];
                ldm4(bfrag_addr(sb + S_BF, wn + ng * 16, s, lane), bf);
                mma_hf(acc[0][2*ng],   af[0], bf[0], bf[1]);
                mma_hf(acc[1][2*ng],   af[1], bf[0], bf[1]);
                mma_hf(acc[0][2*ng+1], af[0], bf[2], bf[3]);
                mma_hf(acc[1][2*ng+1], af[1], bf[2], bf[3]);
            }
        }
        __syncthreads();
    }

#pragma unroll
    for (int mt = 0; mt < 2; ++mt) {
        int c = c0 + wm + mt * 16 + (lane >> 2);
        int nl = wn + (lane & 3) * 2;
        float* o0 = out + ((size_t)n * CD + c) * HW + hw0 + nl;
        float* o1 = out + ((size_t)n * CD + c + 8) * HW + hw0 + nl;
#pragma unroll
        for (int nt = 0; nt < 8; ++nt) {
            float rx = ds[nl + nt * 8], ry = ds[nl + nt * 8 + 1];
            *(float2*)(o0 + nt * 8) = make_float2(acc[mt][nt][0] * rx, acc[mt][nt][1] * ry);
            *(float2*)(o1 + nt * 8) = make_float2(acc[mt][nt][2] * rx, acc[mt][nt][3] * ry);
        }
    }
}

// ----------------------------------------------------------------
extern "C" void kernel_launch(void* const* d_in, const int* in_sizes, int n_in,
                              void* d_out, int out_size) {
    const float* x = (const float*)d_in[0];
    const int* idx = (const int*)d_in[1];
    float* out = (float*)d_out;

    cudaFuncSetAttribute(score_mma, cudaFuncAttributeMaxDynamicSharedMemorySize, SC_SMEM);
    cudaFuncSetAttribute(recon_mma, cudaFuncAttributeMaxDynamicSharedMemorySize, SC_SMEM);

    zero_colsum_kernel<<<1, KA>>>();
    norm_kernel<<<ROWS / 256, 256>>>(x);
    xt_kernel<<<dim3(HW / 32, CD / 32, NB), dim3(32, 8)>>>(x);
    gather_cj<<<(NB * CD * KA) / 256, 256>>>(x, idx);
    gather_jc<<<(NB * KA * CD) / 256, 256>>>(x, idx);

    score_mma<<<dim3(HW / 128, KA / 128, NB), 256, SC_SMEM>>>();   // A0(fp16) + colsum0

    recip_kernel<<<1, KA>>>();                       // c1 (normalized)
    for (int it = 0; it < 3; ++it) {
        sk_pass<<<ROWS / 128, 256>>>();
        recip_kernel<<<1, KA>>>();                   // c2, c3, c4
    }
    scale_s_kernel<<<(NB * CD * KA) / 256, 256>>>(); // S' = S * c4 (fp16)
    dinv_kernel<<<ROWS / 128, 256>>>();              // dinv = 1/(A0 . c4)
    recon_mma<<<dim3(HW / 128, CD / 128, NB), 256, SC_SMEM>>>(out);
}

// round 9
// speedup vs baseline: 1.9586x; 1.1082x over previous
#include <cuda_runtime.h>
#include <cuda_fp16.h>
#include <cstdint>

#define NB 16
#define CD 256
#define HW 4096
#define KA 512
#define ROWS (NB*HW)   // 65536

// ---------------- scratch (__device__ globals; no allocations) ----------------
__device__ __align__(16) __half g_A0[(size_t)ROWS * KA];             // 64 MB (fp16)
__device__ __align__(16) __half g_Xf[(size_t)ROWS * CD];             // X^T*invnorm fp16 [n][hw][c]
__device__ __align__(16) __half g_Sfj[(size_t)NB*KA*CD];             // S fp16 [n][j][c]
__device__ __align__(16) float  g_Scf[(size_t)NB*CD*KA];             // S fp32 [n][c][j]
__device__ __align__(16) __half g_Sck[(size_t)NB*CD*KA];             // S*c fp16 [n][c][j]
__device__ float g_invnorm[ROWS];
__device__ float g_dinv[ROWS];
__device__ float g_colsum[KA];
__device__ float g_cvec[KA];

// ---------------- helpers ----------------
__device__ __forceinline__ uint32_t smem_u32(const void* p) {
    uint32_t a;
    asm("{ .reg .u64 t; cvta.to.shared.u64 t, %1; cvt.u32.u64 %0, t; }" : "=r"(a) : "l"(p));
    return a;
}
__device__ __forceinline__ uint32_t swz(uint32_t o) { return o ^ ((o >> 3) & 0x70); }
__device__ __forceinline__ void ldm4(uint32_t addr, uint32_t r[4]) {
    asm volatile("ldmatrix.sync.aligned.m8n8.x4.shared.b16 {%0,%1,%2,%3}, [%4];"
        : "=r"(r[0]), "=r"(r[1]), "=r"(r[2]), "=r"(r[3]) : "r"(addr));
}
__device__ __forceinline__ void mma_hf(float c[4], const uint32_t a[4],
                                       uint32_t b0, uint32_t b1) {
    asm volatile("mma.sync.aligned.m16n8k16.row.col.f32.f16.f16.f32 "
        "{%0,%1,%2,%3}, {%4,%5,%6,%7}, {%8,%9}, {%0,%1,%2,%3};"
        : "+f"(c[0]), "+f"(c[1]), "+f"(c[2]), "+f"(c[3])
        : "r"(a[0]), "r"(a[1]), "r"(a[2]), "r"(a[3]), "r"(b0), "r"(b1));
}
__device__ __forceinline__ uint32_t afrag_addr(uint32_t base, int mbase, int s, int lane) {
    int row = mbase + (lane & 7) + ((lane >> 3) & 1) * 8;
    int unit = 2 * s + (lane >> 4);
    return base + swz((uint32_t)(row * 128 + unit * 16));
}
__device__ __forceinline__ uint32_t bfrag_addr(uint32_t base, int nbase, int s, int lane) {
    int row = nbase + (lane & 7) + ((lane >> 4) & 1) * 8;
    int unit = 2 * s + ((lane >> 3) & 1);
    return base + swz((uint32_t)(row * 128 + unit * 16));
}
#define CPA16(s, g) asm volatile("cp.async.cg.shared.global [%0], [%1], 16;" :: "r"(s), "l"(g))
#define CP_COMMIT() asm volatile("cp.async.commit_group;" ::: "memory")
#define CP_WAIT1()  asm volatile("cp.async.wait_group 1;" ::: "memory")
#define CP_WAIT0()  asm volatile("cp.async.wait_group 0;" ::: "memory")

// GEMM SMEM: red 512B @0 | stage s @4096+s*32768: AF +0 (16KB), BF +16384 (16KB)
#define G_STG(s) (4096 + (s) * 32768)
#define G_BF 16384
#define G_SMEM (4096 + 65536)   // 69632; 2 CTA/SM = 136KB < 228KB

// ---------------- small kernels ----------------
__global__ void zero_colsum_kernel() { g_colsum[threadIdx.x] = 0.0f; }

// fused: channel L2 norm + transpose + fp16, Xf = x * invnorm  [n][hw][c]
__global__ __launch_bounds__(256) void xtn_kernel(const float* __restrict__ x) {
    __shared__ float t[256][33];
    __shared__ float ps[8][32];
    __shared__ float inv[32];
    int n = blockIdx.y, hw0 = blockIdx.x * 32;
    int tid = threadIdx.x;
    int tx = tid & 31, ty = tid >> 5;
    const float* p = x + (size_t)n * CD * HW + hw0 + tx;
#pragma unroll
    for (int cc = 0; cc < 32; ++cc) {
        int c = cc * 8 + ty;
        t[c][tx] = p[(size_t)c * HW];
    }
    __syncthreads();
    float s = 0.f;
#pragma unroll
    for (int k = 0; k < 32; ++k) {
        float v = t[ty * 32 + k][tx];
        s = fmaf(v, v, s);
    }
    ps[ty][tx] = s;
    __syncthreads();
    if (ty == 0) {
        float a = 0.f;
#pragma unroll
        for (int k = 0; k < 8; ++k) a += ps[k][tx];
        float invn = 1.0f / fmaxf(sqrtf(a), 1e-12f);
        inv[tx] = invn;
        g_invnorm[n * HW + hw0 + tx] = invn;
    }
    __syncthreads();
    int c2 = tid & 127, hwp = tid >> 7;
#pragma unroll
    for (int it = 0; it < 16; ++it) {
        int hw = it * 2 + hwp;
        float iv = inv[hw];
        float v0 = t[c2 * 2][hw] * iv;
        float v1 = t[c2 * 2 + 1][hw] * iv;
        *(__half2*)(&g_Xf[((size_t)n * HW + hw0 + hw) * CD + c2 * 2]) =
            __halves2half2(__float2half(v0), __float2half(v1));
    }
}

__global__ void gather_cj(const float* __restrict__ x, const int* __restrict__ idx) {
    int t = blockIdx.x * blockDim.x + threadIdx.x;   // [n][c][j], j fastest
    int j = t & (KA - 1);
    int nc = t >> 9;
    int n = nc >> 8;
    int pos = idx[j];
    g_Scf[t] = x[(size_t)nc * HW + pos] * g_invnorm[n * HW + pos];
}
__global__ void gather_jc(const float* __restrict__ x, const int* __restrict__ idx) {
    int t = blockIdx.x * blockDim.x + threadIdx.x;   // [n][j][c], c fastest
    int c = t & (CD - 1);
    int nj = t >> 8;
    int j = nj & (KA - 1);
    int n = nj >> 9;
    int pos = idx[j];
    g_Sfj[t] = __float2half(x[((size_t)n * CD + c) * HW + pos] * g_invnorm[n * HW + pos]);
}

// c = (1/colsum) normalized by max (output scale-invariant); reset colsum
__global__ void recip_kernel() {
    __shared__ float sm[KA];
    int j = threadIdx.x;
    float c = 1.0f / fmaxf(g_colsum[j], 1e-30f);
    sm[j] = c;
    __syncthreads();
    for (int s = 256; s > 0; s >>= 1) {
        if (j < s) sm[j] = fmaxf(sm[j], sm[j + s]);
        __syncthreads();
    }
    g_cvec[j] = c / sm[0];
    g_colsum[j] = 0.0f;
}

// S' = fp16(S_float * c)  [n][c][j]
__global__ void scale_s_kernel() {
    int t = blockIdx.x * blockDim.x + threadIdx.x;
    int j = t & (KA - 1);
    g_Sck[t] = __float2half(g_Scf[t] * g_cvec[j]);
}

// dinv_i = 1 / (A0_i . c)
__global__ __launch_bounds__(256) void dinv_kernel() {
    int tid = threadIdx.x;
    int warp = tid >> 5, lane = tid & 31;
    float cv[16];
#pragma unroll
    for (int e = 0; e < 8; ++e) { cv[e] = g_cvec[lane * 8 + e]; cv[8 + e] = g_cvec[256 + lane * 8 + e]; }
    size_t rbase = (size_t)blockIdx.x * 128 + warp * 16;
    for (int t = 0; t < 16; ++t) {
        const uint4* row = (const uint4*)(g_A0 + (rbase + t) * KA);
        uint4 u0 = row[lane], u1 = row[lane + 32];
        const __half2* h0 = (const __half2*)&u0;
        const __half2* h1 = (const __half2*)&u1;
        float d = 0.0f;
#pragma unroll
        for (int k = 0; k < 4; ++k) {
            float2 f0 = __half22float2(h0[k]);
            float2 f1 = __half22float2(h1[k]);
            d = fmaf(f0.x, cv[2*k], d);   d = fmaf(f0.y, cv[2*k+1], d);
            d = fmaf(f1.x, cv[8+2*k], d); d = fmaf(f1.y, cv[8+2*k+1], d);
        }
#pragma unroll
        for (int s = 16; s > 0; s >>= 1) d += __shfl_xor_sync(0xffffffffu, d, s);
        if (lane == 0) g_dinv[rbase + t] = 1.0f / fmaxf(d, 1e-30f);
    }
}

// fused Sinkhorn pass on fp16 A0
__global__ __launch_bounds__(256) void sk_pass() {
    __shared__ float cred[KA];
    int tid = threadIdx.x;
    cred[tid] = 0.0f; cred[tid + 256] = 0.0f;
    __syncthreads();
    int warp = tid >> 5, lane = tid & 31;
    float cv[16];
#pragma unroll
    for (int e = 0; e < 8; ++e) { cv[e] = g_cvec[lane * 8 + e]; cv[8 + e] = g_cvec[256 + lane * 8 + e]; }
    float ca[16];
#pragma unroll
    for (int e = 0; e < 16; ++e) ca[e] = 0.0f;
    size_t rbase = (size_t)blockIdx.x * 128 + warp * 16;
    for (int t = 0; t < 16; ++t) {
        const uint4* row = (const uint4*)(g_A0 + (rbase + t) * KA);
        uint4 u0 = row[lane], u1 = row[lane + 32];
        float a[16];
        {
            const __half2* h0 = (const __half2*)&u0;
            const __half2* h1 = (const __half2*)&u1;
#pragma unroll
            for (int k = 0; k < 4; ++k) {
                float2 f0 = __half22float2(h0[k]);
                float2 f1 = __half22float2(h1[k]);
                a[2*k] = f0.x; a[2*k+1] = f0.y;
                a[8 + 2*k] = f1.x; a[8 + 2*k+1] = f1.y;
            }
        }
        float d = 0.0f;
#pragma unroll
        for (int e = 0; e < 16; ++e) d = fmaf(a[e], cv[e], d);
#pragma unroll
        for (int s = 16; s > 0; s >>= 1) d += __shfl_xor_sync(0xffffffffu, d, s);
        float r = 1.0f / fmaxf(d, 1e-30f);
#pragma unroll
        for (int e = 0; e < 16; ++e) ca[e] = fmaf(r, a[e], ca[e]);
    }
#pragma unroll
    for (int e = 0; e < 8; ++e) {
        atomicAdd(&cred[lane * 8 + e], ca[e]);
        atomicAdd(&cred[256 + lane * 8 + e], ca[8 + e]);
    }
    __syncthreads();
    atomicAdd(&g_colsum[tid], cred[tid]);
    atomicAdd(&g_colsum[tid + 256], cred[tid + 256]);
}

// ================= score GEMM: fp16 mma + 2-stage cp.async + fused colsum =================
__global__ __launch_bounds__(256, 2) void score_mma() {
    extern __shared__ char smem[];
    uint32_t sb = smem_u32(smem);
    float* colred = (float*)smem;
    int tid = threadIdx.x, lane = tid & 31, w = tid >> 5;
    int n = blockIdx.z, hw0 = blockIdx.x * 128, j0 = blockIdx.y * 128;
    int wm = (w & 3) * 32, wn = (w >> 2) * 64;

    float acc[2][8][4];
#pragma unroll
    for (int a = 0; a < 2; ++a)
#pragma unroll
        for (int b = 0; b < 8; ++b)
#pragma unroll
            for (int c = 0; c < 4; ++c) acc[a][b][c] = 0.0f;

    int crow = tid >> 1, chalf = tid & 1;
    const uint4* aF = (const uint4*)(g_Xf + ((size_t)n * HW + hw0 + crow) * CD);
    const uint4* bF = (const uint4*)(g_Sfj + ((size_t)n * KA + j0 + crow) * CD);
    uint32_t loff = swz((uint32_t)(crow * 128 + chalf * 64));   // 4 consecutive units share swizzle row

    auto issue = [&](int ch, int st) {
        uint32_t base = sb + G_STG(st);
#pragma unroll
        for (int q = 0; q < 4; ++q) {
            int unit = chalf * 4 + q;
            uint32_t off = swz((uint32_t)(crow * 128 + unit * 16));
            int gi = ch * 8 + unit;
            CPA16(base + off, aF + gi);
            CPA16(base + G_BF + off, bF + gi);
        }
    };
    (void)loff;

    issue(0, 0); CP_COMMIT();
#pragma unroll 1
    for (int ch = 0; ch < 4; ++ch) {
        if (ch < 3) { issue(ch + 1, (ch + 1) & 1); CP_COMMIT(); CP_WAIT1(); }
        else CP_WAIT0();
        __syncthreads();
        uint32_t tb = sb + G_STG(ch & 1);
#pragma unroll
        for (int s = 0; s < 4; ++s) {
            uint32_t af[2][4];
#pragma unroll
            for (int mt = 0; mt < 2; ++mt)
                ldm4(afrag_addr(tb, wm + mt * 16, s, lane), af[mt]);
#pragma unroll
            for (int ng = 0; ng < 4; ++ng) {
                uint32_t bf[4];
                ldm4(bfrag_addr(tb + G_BF, wn + ng * 16, s, lane), bf);
                mma_hf(acc[0][2*ng],   af[0], bf[0], bf[1]);
                mma_hf(acc[1][2*ng],   af[1], bf[0], bf[1]);
                mma_hf(acc[0][2*ng+1], af[0], bf[2], bf[3]);
                mma_hf(acc[1][2*ng+1], af[1], bf[2], bf[3]);
            }
        }
        __syncthreads();
    }

    // epilogue: acc is cosine; exp(acc/T) -> fp16 store + fused first column-sum
    if (tid < 128) colred[tid] = 0.0f;
    __syncthreads();
    const float sc = 1.0f / 0.3f;
    float colp[16];
#pragma unroll
    for (int e = 0; e < 16; ++e) colp[e] = 0.0f;
#pragma unroll
    for (int mt = 0; mt < 2; ++mt) {
        int i0 = n * HW + hw0 + wm + mt * 16 + (lane >> 2);
        int i1 = i0 + 8;
        __half* r0 = g_A0 + (size_t)i0 * KA + j0 + wn + (lane & 3) * 2;
        __half* r1 = g_A0 + (size_t)i1 * KA + j0 + wn + (lane & 3) * 2;
#pragma unroll
        for (int nt = 0; nt < 8; ++nt) {
            __half h0 = __float2half(__expf(acc[mt][nt][0] * sc));
            __half h1 = __float2half(__expf(acc[mt][nt][1] * sc));
            __half h2 = __float2half(__expf(acc[mt][nt][2] * sc));
            __half h3 = __float2half(__expf(acc[mt][nt][3] * sc));
            *(__half2*)(r0 + nt * 8) = __halves2half2(h0, h1);
            *(__half2*)(r1 + nt * 8) = __halves2half2(h2, h3);
            colp[nt * 2]     += __half2float(h0) + __half2float(h2);
            colp[nt * 2 + 1] += __half2float(h1) + __half2float(h3);
        }
    }
#pragma unroll
    for (int nt = 0; nt < 8; ++nt) {
        int cl = wn + (lane & 3) * 2 + nt * 8;
        atomicAdd(&colred[cl], colp[nt * 2]);
        atomicAdd(&colred[cl + 1], colp[nt * 2 + 1]);
    }
    __syncthreads();
    if (tid < 128) atomicAdd(&g_colsum[j0 + tid], colred[tid]);
}

// ================= reconstruct GEMM: fp16 mma + 2-stage cp.async =================
__global__ __launch_bounds__(256, 2) void recon_mma(float* __restrict__ out) {
    extern __shared__ char smem[];
    uint32_t sb = smem_u32(smem);
    float* ds = (float*)smem;
    int tid = threadIdx.x, lane = tid & 31, w = tid >> 5;
    int n = blockIdx.z, hw0 = blockIdx.x * 128, c0 = blockIdx.y * 128;
    int wm = (w & 3) * 32, wn = (w >> 2) * 64;

    if (tid < 128) ds[tid] = g_dinv[n * HW + hw0 + tid];

    float acc[2][8][4];
#pragma unroll
    for (int a = 0; a < 2; ++a)
#pragma unroll
        for (int b = 0; b < 8; ++b)
#pragma unroll
            for (int c = 0; c < 4; ++c) acc[a][b][c] = 0.0f;

    int crow = tid >> 1, chalf = tid & 1;
    const uint4* aF = (const uint4*)(g_Sck + ((size_t)n * CD + c0 + crow) * KA);
    const uint4* bF = (const uint4*)(g_A0 + ((size_t)(n * HW + hw0 + crow)) * KA);

    auto issue = [&](int ch, int st) {
        uint32_t base = sb + G_STG(st);
#pragma unroll
        for (int q = 0; q < 4; ++q) {
            int unit = chalf * 4 + q;
            uint32_t off = swz((uint32_t)(crow * 128 + unit * 16));
            int gi = ch * 8 + unit;
            CPA16(base + off, aF + gi);
            CPA16(base + G_BF + off, bF + gi);
        }
    };

    issue(0, 0); CP_COMMIT();
#pragma unroll 1
    for (int ch = 0; ch < 8; ++ch) {
        if (ch < 7) { issue(ch + 1, (ch + 1) & 1); CP_COMMIT(); CP_WAIT1(); }
        else CP_WAIT0();
        __syncthreads();
        uint32_t tb = sb + G_STG(ch & 1);
#pragma unroll
        for (int s = 0; s < 4; ++s) {
            uint32_t af[2][4];
#pragma unroll
            for (int mt = 0; mt < 2; ++mt)
                ldm4(afrag_addr(tb, wm + mt * 16, s, lane), af[mt]);
#pragma unroll
            for (int ng = 0; ng < 4; ++ng) {
                uint32_t bf[4];
                ldm4(bfrag_addr(tb + G_BF, wn + ng * 16, s, lane), bf);
                mma_hf(acc[0][2*ng],   af[0], bf[0], bf[1]);
                mma_hf(acc[1][2*ng],   af[1], bf[0], bf[1]);
                mma_hf(acc[0][2*ng+1], af[0], bf[2], bf[3]);
                mma_hf(acc[1][2*ng+1], af[1], bf[2], bf[3]);
            }
        }
        __syncthreads();
    }

#pragma unroll
    for (int mt = 0; mt < 2; ++mt) {
        int c = c0 + wm + mt * 16 + (lane >> 2);
        int nl = wn + (lane & 3) * 2;
        float* o0 = out + ((size_t)n * CD + c) * HW + hw0 + nl;
        float* o1 = out + ((size_t)n * CD + c + 8) * HW + hw0 + nl;
#pragma unroll
        for (int nt = 0; nt < 8; ++nt) {
            float rx = ds[nl + nt * 8], ry = ds[nl + nt * 8 + 1];
            *(float2*)(o0 + nt * 8) = make_float2(acc[mt][nt][0] * rx, acc[mt][nt][1] * ry);
            *(float2*)(o1 + nt * 8) = make_float2(acc[mt][nt][2] * rx, acc[mt][nt][3] * ry);
        }
    }
}

// ----------------------------------------------------------------
extern "C" void kernel_launch(void* const* d_in, const int* in_sizes, int n_in,
                              void* d_out, int out_size) {
    const float* x = (const float*)d_in[0];
    const int* idx = (const int*)d_in[1];
    float* out = (float*)d_out;

    cudaFuncSetAttribute(score_mma, cudaFuncAttributeMaxDynamicSharedMemorySize, G_SMEM);
    cudaFuncSetAttribute(recon_mma, cudaFuncAttributeMaxDynamicSharedMemorySize, G_SMEM);

    zero_colsum_kernel<<<1, KA>>>();
    xtn_kernel<<<dim3(HW / 32, NB), 256>>>(x);         // norm + transpose + fp16 (fused)
    gather_cj<<<(NB * CD * KA) / 256, 256>>>(x, idx);
    gather_jc<<<(NB * KA * CD) / 256, 256>>>(x, idx);

    score_mma<<<dim3(HW / 128, KA / 128, NB), 256, G_SMEM>>>();   // A0(fp16) + colsum0

    recip_kernel<<<1, KA>>>();                       // c1 (normalized)
    for (int it = 0; it < 3; ++it) {
        sk_pass<<<ROWS / 128, 256>>>();
        recip_kernel<<<1, KA>>>();                   // c2, c3, c4
    }
    scale_s_kernel<<<(NB * CD * KA) / 256, 256>>>(); // S' = S * c4 (fp16)
    dinv_kernel<<<ROWS / 128, 256>>>();              // dinv = 1/(A0 . c4)
    recon_mma<<<dim3(HW / 128, CD / 128, NB), 256, G_SMEM>>>(out);
}

// round 10
// speedup vs baseline: 2.0881x; 1.0661x over previous
#include <cuda_runtime.h>
#include <cuda_fp16.h>
#include <cstdint>

#define NB 16
#define CD 256
#define HW 4096
#define KA 512
#define ROWS (NB*HW)   // 65536

// ---------------- scratch (__device__ globals; no allocations) ----------------
__device__ __align__(16) __half g_A0[(size_t)ROWS * KA];             // 64 MB (fp16)
__device__ __align__(16) __half g_Xf[(size_t)ROWS * CD];             // X^T*invnorm fp16 [n][hw][c]
__device__ __align__(16) __half g_Sfj[(size_t)NB*KA*CD];             // S fp16 [n][j][c]
__device__ __align__(16) float  g_Scf[(size_t)NB*CD*KA];             // S fp32 [n][c][j]
__device__ __align__(16) __half g_Sck[(size_t)NB*CD*KA];             // S*c fp16 [n][c][j]
__device__ float g_invnorm[ROWS];
__device__ float g_dinv[ROWS];
__device__ float g_colsum[KA];
__device__ float g_cvec[KA];

// ---------------- helpers ----------------
__device__ __forceinline__ uint32_t smem_u32(const void* p) {
    uint32_t a;
    asm("{ .reg .u64 t; cvta.to.shared.u64 t, %1; cvt.u32.u64 %0, t; }" : "=r"(a) : "l"(p));
    return a;
}
__device__ __forceinline__ uint32_t swz(uint32_t o) { return o ^ ((o >> 3) & 0x70); }
__device__ __forceinline__ void ldm4(uint32_t addr, uint32_t r[4]) {
    asm volatile("ldmatrix.sync.aligned.m8n8.x4.shared.b16 {%0,%1,%2,%3}, [%4];"
        : "=r"(r[0]), "=r"(r[1]), "=r"(r[2]), "=r"(r[3]) : "r"(addr));
}
__device__ __forceinline__ void mma_hf(float c[4], const uint32_t a[4],
                                       uint32_t b0, uint32_t b1) {
    asm volatile("mma.sync.aligned.m16n8k16.row.col.f32.f16.f16.f32 "
        "{%0,%1,%2,%3}, {%4,%5,%6,%7}, {%8,%9}, {%0,%1,%2,%3};"
        : "+f"(c[0]), "+f"(c[1]), "+f"(c[2]), "+f"(c[3])
        : "r"(a[0]), "r"(a[1]), "r"(a[2]), "r"(a[3]), "r"(b0), "r"(b1));
}
__device__ __forceinline__ uint32_t afrag_addr(uint32_t base, int mbase, int s, int lane) {
    int row = mbase + (lane & 7) + ((lane >> 3) & 1) * 8;
    int unit = 2 * s + (lane >> 4);
    return base + swz((uint32_t)(row * 128 + unit * 16));
}
__device__ __forceinline__ uint32_t bfrag_addr(uint32_t base, int nbase, int s, int lane) {
    int row = nbase + (lane & 7) + ((lane >> 4) & 1) * 8;
    int unit = 2 * s + ((lane >> 3) & 1);
    return base + swz((uint32_t)(row * 128 + unit * 16));
}
#define CPA16(s, g) asm volatile("cp.async.cg.shared.global [%0], [%1], 16;" :: "r"(s), "l"(g))
#define CP_COMMIT() asm volatile("cp.async.commit_group;" ::: "memory")
#define CP_WAIT0()  asm volatile("cp.async.wait_group 0;" ::: "memory")

// GEMM SMEM: red 512B @0 | stage s @4096+s*32768: AF +0 (16KB), BF +16384 (16KB)
#define G_STG(s) (4096 + (s) * 32768)
#define G_BF 16384
#define G_SMEM (4096 + 65536)   // 69632; 2 CTA/SM

// ---------------- small kernels ----------------

// fused: channel L2 norm + transpose + fp16, Xf = x * invnorm; block(0,0) zeroes colsum
__global__ __launch_bounds__(256) void xtn_kernel(const float* __restrict__ x) {
    __shared__ float t[256][33];
    __shared__ float ps[8][32];
    __shared__ float inv[32];
    int n = blockIdx.y, hw0 = blockIdx.x * 32;
    int tid = threadIdx.x;
    if (blockIdx.x == 0 && blockIdx.y == 0) {
        g_colsum[tid] = 0.0f; g_colsum[tid + 256] = 0.0f;
    }
    int tx = tid & 31, ty = tid >> 5;
    const float* p = x + (size_t)n * CD * HW + hw0 + tx;
#pragma unroll
    for (int cc = 0; cc < 32; ++cc) {
        int c = cc * 8 + ty;
        t[c][tx] = p[(size_t)c * HW];
    }
    __syncthreads();
    float s = 0.f;
#pragma unroll
    for (int k = 0; k < 32; ++k) {
        float v = t[ty * 32 + k][tx];
        s = fmaf(v, v, s);
    }
    ps[ty][tx] = s;
    __syncthreads();
    if (ty == 0) {
        float a = 0.f;
#pragma unroll
        for (int k = 0; k < 8; ++k) a += ps[k][tx];
        float invn = 1.0f / fmaxf(sqrtf(a), 1e-12f);
        inv[tx] = invn;
        g_invnorm[n * HW + hw0 + tx] = invn;
    }
    __syncthreads();
    int c2 = tid & 127, hwp = tid >> 7;
#pragma unroll
    for (int it = 0; it < 16; ++it) {
        int hw = it * 2 + hwp;
        float iv = inv[hw];
        float v0 = t[c2 * 2][hw] * iv;
        float v1 = t[c2 * 2 + 1][hw] * iv;
        *(__half2*)(&g_Xf[((size_t)n * HW + hw0 + hw) * CD + c2 * 2]) =
            __halves2half2(__float2half(v0), __float2half(v1));
    }
}

// merged gather: one scattered read of anchors -> Scf (fp32 [c][j]) + Sfj (fp16 [j][c])
// tile: 32 c x 128 j per block; smem transpose with pad.
__global__ __launch_bounds__(256) void gather_both(const float* __restrict__ x,
                                                   const int* __restrict__ idx) {
    __shared__ float t[32][129];
    __shared__ int   pos_s[128];
    __shared__ float inv_s[128];
    int n = blockIdx.z, c0 = blockIdx.y * 32, j0 = blockIdx.x * 128;
    int tid = threadIdx.x;
    if (tid < 128) {
        int p = idx[j0 + tid];
        pos_s[tid] = p;
        inv_s[tid] = g_invnorm[n * HW + p];
    }
    __syncthreads();
#pragma unroll
    for (int it = 0; it < 16; ++it) {
        int e = tid + it * 256;          // 0..4095
        int c = e >> 7, j = e & 127;
        float v = x[((size_t)(n * CD + c0 + c)) * HW + pos_s[j]] * inv_s[j];
        g_Scf[((size_t)(n * CD + c0 + c)) * KA + j0 + j] = v;
        t[c][j] = v;
    }
    __syncthreads();
#pragma unroll
    for (int it = 0; it < 16; ++it) {
        int e = tid + it * 256;
        int j = e >> 5, c = e & 31;
        g_Sfj[((size_t)(n * KA + j0 + j)) * CD + c0 + c] = __float2half(t[c][j]);
    }
}

// c = (1/colsum) normalized by max (output scale-invariant); reset colsum
__global__ void recip_kernel() {
    __shared__ float sm[KA];
    int j = threadIdx.x;
    float c = 1.0f / fmaxf(g_colsum[j], 1e-30f);
    sm[j] = c;
    __syncthreads();
    for (int s = 256; s > 0; s >>= 1) {
        if (j < s) sm[j] = fmaxf(sm[j], sm[j + s]);
        __syncthreads();
    }
    g_cvec[j] = c / sm[0];
    g_colsum[j] = 0.0f;
}

// merged: dinv (blocks 0..511) + S' = fp16(S*c) (blocks 512..)
__global__ __launch_bounds__(256) void prep_recon() {
    int tid = threadIdx.x;
    if (blockIdx.x < ROWS / 128) {
        int warp = tid >> 5, lane = tid & 31;
        float cv[16];
#pragma unroll
        for (int e = 0; e < 8; ++e) {
            cv[e] = g_cvec[lane * 8 + e];
            cv[8 + e] = g_cvec[256 + lane * 8 + e];
        }
        size_t rbase = (size_t)blockIdx.x * 128 + warp * 16;
        for (int t = 0; t < 16; ++t) {
            const uint4* row = (const uint4*)(g_A0 + (rbase + t) * KA);
            uint4 u0 = row[lane], u1 = row[lane + 32];
            const __half2* h0 = (const __half2*)&u0;
            const __half2* h1 = (const __half2*)&u1;
            float d = 0.0f;
#pragma unroll
            for (int k = 0; k < 4; ++k) {
                float2 f0 = __half22float2(h0[k]);
                float2 f1 = __half22float2(h1[k]);
                d = fmaf(f0.x, cv[2*k], d);   d = fmaf(f0.y, cv[2*k+1], d);
                d = fmaf(f1.x, cv[8+2*k], d); d = fmaf(f1.y, cv[8+2*k+1], d);
            }
#pragma unroll
            for (int s = 16; s > 0; s >>= 1) d += __shfl_xor_sync(0xffffffffu, d, s);
            if (lane == 0) g_dinv[rbase + t] = 1.0f / fmaxf(d, 1e-30f);
        }
    } else {
        int t = (blockIdx.x - ROWS / 128) * 256 + tid;
        int j = t & (KA - 1);
        g_Sck[t] = __float2half(g_Scf[t] * g_cvec[j]);
    }
}

// fused Sinkhorn pass on fp16 A0
__global__ __launch_bounds__(256) void sk_pass() {
    __shared__ float cred[KA];
    int tid = threadIdx.x;
    cred[tid] = 0.0f; cred[tid + 256] = 0.0f;
    __syncthreads();
    int warp = tid >> 5, lane = tid & 31;
    float cv[16];
#pragma unroll
    for (int e = 0; e < 8; ++e) { cv[e] = g_cvec[lane * 8 + e]; cv[8 + e] = g_cvec[256 + lane * 8 + e]; }
    float ca[16];
#pragma unroll
    for (int e = 0; e < 16; ++e) ca[e] = 0.0f;
    size_t rbase = (size_t)blockIdx.x * 128 + warp * 16;
    for (int t = 0; t < 16; ++t) {
        const uint4* row = (const uint4*)(g_A0 + (rbase + t) * KA);
        uint4 u0 = row[lane], u1 = row[lane + 32];
        float a[16];
        {
            const __half2* h0 = (const __half2*)&u0;
            const __half2* h1 = (const __half2*)&u1;
#pragma unroll
            for (int k = 0; k < 4; ++k) {
                float2 f0 = __half22float2(h0[k]);
                float2 f1 = __half22float2(h1[k]);
                a[2*k] = f0.x; a[2*k+1] = f0.y;
                a[8 + 2*k] = f1.x; a[8 + 2*k+1] = f1.y;
            }
        }
        float d = 0.0f;
#pragma unroll
        for (int e = 0; e < 16; ++e) d = fmaf(a[e], cv[e], d);
#pragma unroll
        for (int s = 16; s > 0; s >>= 1) d += __shfl_xor_sync(0xffffffffu, d, s);
        float r = 1.0f / fmaxf(d, 1e-30f);
#pragma unroll
        for (int e = 0; e < 16; ++e) ca[e] = fmaf(r, a[e], ca[e]);
    }
#pragma unroll
    for (int e = 0; e < 8; ++e) {
        atomicAdd(&cred[lane * 8 + e], ca[e]);
        atomicAdd(&cred[256 + lane * 8 + e], ca[8 + e]);
    }
    __syncthreads();
    atomicAdd(&g_colsum[tid], cred[tid]);
    atomicAdd(&g_colsum[tid + 256], cred[tid + 256]);
}

// ================= score GEMM: fp16 mma, single-sync cp.async pipeline =================
__global__ __launch_bounds__(256, 2) void score_mma() {
    extern __shared__ char smem[];
    uint32_t sb = smem_u32(smem);
    float* colred = (float*)smem;
    int tid = threadIdx.x, lane = tid & 31, w = tid >> 5;
    int n = blockIdx.z, hw0 = blockIdx.x * 128, j0 = blockIdx.y * 128;
    int wm = (w & 3) * 32, wn = (w >> 2) * 64;

    float acc[2][8][4];
#pragma unroll
    for (int a = 0; a < 2; ++a)
#pragma unroll
        for (int b = 0; b < 8; ++b)
#pragma unroll
            for (int c = 0; c < 4; ++c) acc[a][b][c] = 0.0f;

    int crow = tid >> 1, chalf = tid & 1;
    const uint4* aF = (const uint4*)(g_Xf + ((size_t)n * HW + hw0 + crow) * CD);
    const uint4* bF = (const uint4*)(g_Sfj + ((size_t)n * KA + j0 + crow) * CD);

    auto issue = [&](int ch, int st) {
        uint32_t base = sb + G_STG(st);
#pragma unroll
        for (int q = 0; q < 4; ++q) {
            int unit = chalf * 4 + q;
            uint32_t off = swz((uint32_t)(crow * 128 + unit * 16));
            int gi = ch * 8 + unit;
            CPA16(base + off, aF + gi);
            CPA16(base + G_BF + off, bF + gi);
        }
    };

    issue(0, 0); CP_COMMIT();
#pragma unroll 1
    for (int ch = 0; ch < 4; ++ch) {
        CP_WAIT0();
        __syncthreads();
        if (ch + 1 < 4) { issue(ch + 1, (ch + 1) & 1); CP_COMMIT(); }
        uint32_t tb = sb + G_STG(ch & 1);
#pragma unroll
        for (int s = 0; s < 4; ++s) {
            uint32_t af[2][4];
#pragma unroll
            for (int mt = 0; mt < 2; ++mt)
                ldm4(afrag_addr(tb, wm + mt * 16, s, lane), af[mt]);
#pragma unroll
            for (int ng = 0; ng < 4; ++ng) {
                uint32_t bf[4];
                ldm4(bfrag_addr(tb + G_BF, wn + ng * 16, s, lane), bf);
                mma_hf(acc[0][2*ng],   af[0], bf[0], bf[1]);
                mma_hf(acc[1][2*ng],   af[1], bf[0], bf[1]);
                mma_hf(acc[0][2*ng+1], af[0], bf[2], bf[3]);
                mma_hf(acc[1][2*ng+1], af[1], bf[2], bf[3]);
            }
        }
    }

    // epilogue: acc is cosine; exp(acc/T) -> fp16 store + fused first column-sum
    __syncthreads();
    if (tid < 128) colred[tid] = 0.0f;
    __syncthreads();
    const float sc = 1.0f / 0.3f;
    float colp[16];
#pragma unroll
    for (int e = 0; e < 16; ++e) colp[e] = 0.0f;
#pragma unroll
    for (int mt = 0; mt < 2; ++mt) {
        int i0 = n * HW + hw0 + wm + mt * 16 + (lane >> 2);
        int i1 = i0 + 8;
        __half* r0 = g_A0 + (size_t)i0 * KA + j0 + wn + (lane & 3) * 2;
        __half* r1 = g_A0 + (size_t)i1 * KA + j0 + wn + (lane & 3) * 2;
#pragma unroll
        for (int nt = 0; nt < 8; ++nt) {
            __half h0 = __float2half(__expf(acc[mt][nt][0] * sc));
            __half h1 = __float2half(__expf(acc[mt][nt][1] * sc));
            __half h2 = __float2half(__expf(acc[mt][nt][2] * sc));
            __half h3 = __float2half(__expf(acc[mt][nt][3] * sc));
            *(__half2*)(r0 + nt * 8) = __halves2half2(h0, h1);
            *(__half2*)(r1 + nt * 8) = __halves2half2(h2, h3);
            colp[nt * 2]     += __half2float(h0) + __half2float(h2);
            colp[nt * 2 + 1] += __half2float(h1) + __half2float(h3);
        }
    }
#pragma unroll
    for (int nt = 0; nt < 8; ++nt) {
        int cl = wn + (lane & 3) * 2 + nt * 8;
        atomicAdd(&colred[cl], colp[nt * 2]);
        atomicAdd(&colred[cl + 1], colp[nt * 2 + 1]);
    }
    __syncthreads();
    if (tid < 128) atomicAdd(&g_colsum[j0 + tid], colred[tid]);
}

// ================= reconstruct GEMM: fp16 mma, single-sync cp.async pipeline =================
__global__ __launch_bounds__(256, 2) void recon_mma(float* __restrict__ out) {
    extern __shared__ char smem[];
    uint32_t sb = smem_u32(smem);
    float* ds = (float*)smem;
    int tid = threadIdx.x, lane = tid & 31, w = tid >> 5;
    int n = blockIdx.z, hw0 = blockIdx.x * 128, c0 = blockIdx.y * 128;
    int wm = (w & 3) * 32, wn = (w >> 2) * 64;

    if (tid < 128) ds[tid] = g_dinv[n * HW + hw0 + tid];

    float acc[2][8][4];
#pragma unroll
    for (int a = 0; a < 2; ++a)
#pragma unroll
        for (int b = 0; b < 8; ++b)
#pragma unroll
            for (int c = 0; c < 4; ++c) acc[a][b][c] = 0.0f;

    int crow = tid >> 1, chalf = tid & 1;
    const uint4* aF = (const uint4*)(g_Sck + ((size_t)n * CD + c0 + crow) * KA);
    const uint4* bF = (const uint4*)(g_A0 + ((size_t)(n * HW + hw0 + crow)) * KA);

    auto issue = [&](int ch, int st) {
        uint32_t base = sb + G_STG(st);
#pragma unroll
        for (int q = 0; q < 4; ++q) {
            int unit = chalf * 4 + q;
            uint32_t off = swz((uint32_t)(crow * 128 + unit * 16));
            int gi = ch * 8 + unit;
            CPA16(base + off, aF + gi);
            CPA16(base + G_BF + off, bF + gi);
        }
    };

    issue(0, 0); CP_COMMIT();
#pragma unroll 1
    for (int ch = 0; ch < 8; ++ch) {
        CP_WAIT0();
        __syncthreads();
        if (ch + 1 < 8) { issue(ch + 1, (ch + 1) & 1); CP_COMMIT(); }
        uint32_t tb = sb + G_STG(ch & 1);
#pragma unroll
        for (int s = 0; s < 4; ++s) {
            uint32_t af[2][4];
#pragma unroll
            for (int mt = 0; mt < 2; ++mt)
                ldm4(afrag_addr(tb, wm + mt * 16, s, lane), af[mt]);
#pragma unroll
            for (int ng = 0; ng < 4; ++ng) {
                uint32_t bf[4];
                ldm4(bfrag_addr(tb + G_BF, wn + ng * 16, s, lane), bf);
                mma_hf(acc[0][2*ng],   af[0], bf[0], bf[1]);
                mma_hf(acc[1][2*ng],   af[1], bf[0], bf[1]);
                mma_hf(acc[0][2*ng+1], af[0], bf[2], bf[3]);
                mma_hf(acc[1][2*ng+1], af[1], bf[2], bf[3]);
            }
        }
    }

#pragma unroll
    for (int mt = 0; mt < 2; ++mt) {
        int c = c0 + wm + mt * 16 + (lane >> 2);
        int nl = wn + (lane & 3) * 2;
        float* o0 = out + ((size_t)n * CD + c) * HW + hw0 + nl;
        float* o1 = out + ((size_t)n * CD + c + 8) * HW + hw0 + nl;
#pragma unroll
        for (int nt = 0; nt < 8; ++nt) {
            float rx = ds[nl + nt * 8], ry = ds[nl + nt * 8 + 1];
            *(float2*)(o0 + nt * 8) = make_float2(acc[mt][nt][0] * rx, acc[mt][nt][1] * ry);
            *(float2*)(o1 + nt * 8) = make_float2(acc[mt][nt][2] * rx, acc[mt][nt][3] * ry);
        }
    }
}

// ----------------------------------------------------------------
extern "C" void kernel_launch(void* const* d_in, const int* in_sizes, int n_in,
                              void* d_out, int out_size) {
    const float* x = (const float*)d_in[0];
    const int* idx = (const int*)d_in[1];
    float* out = (float*)d_out;

    cudaFuncSetAttribute(score_mma, cudaFuncAttributeMaxDynamicSharedMemorySize, G_SMEM);
    cudaFuncSetAttribute(recon_mma, cudaFuncAttributeMaxDynamicSharedMemorySize, G_SMEM);

    xtn_kernel<<<dim3(HW / 32, NB), 256>>>(x);          // norm + transpose + colsum zero
    gather_both<<<dim3(KA / 128, CD / 32, NB), 256>>>(x, idx);

    score_mma<<<dim3(HW / 128, KA / 128, NB), 256, G_SMEM>>>();   // A0(fp16) + colsum0

    recip_kernel<<<1, KA>>>();                       // c1 (normalized)
    for (int it = 0; it < 3; ++it) {
        sk_pass<<<ROWS / 128, 256>>>();
        recip_kernel<<<1, KA>>>();                   // c2, c3, c4
    }
    prep_recon<<<ROWS / 128 + (NB * CD * KA) / 256, 256>>>();   // dinv + S*c
    recon_mma<<<dim3(HW / 128, CD / 128, NB), 256, G_SMEM>>>(out);
}